// round 7
// baseline (speedup 1.0000x reference)
#include <cuda_runtime.h>
#include <cuda_bf16.h>
#include <cuda_fp16.h>
#include <cstdint>
#include <math.h>

// Problem dims (fixed by the reference)
#define BB 64
#define TT 512
#define DD 2048
#define H1C 256
#define H2C 128
#define H3C 64

#define NCL 16           // cluster CTAs
#define TOTS (TT + 2)

// ---------------- scratch (static device buffers; no allocation) ----------------
__device__ __align__(16) float g_xg1[(size_t)BB * TT * 4 * H1C];   // 32768 x 1024
__device__ __align__(16) __nv_bfloat16 g_xbf[(size_t)BB * TT * DD];
__device__ __align__(16) __nv_bfloat16 g_W1bf[4 * H1C * DD];
__device__ __align__(16) float g_h3[BB * H3C];        // layer-3 last h (fp32)
// h ping-pong fragment buffers (fp16 mma A-fragment layout, u32 units)
__device__ __align__(16) uint32_t g_b1[2][8192];      // h1: 16 kb x 512 u32
__device__ __align__(16) uint32_t g_b2[2][4096];      // h2:  8 kb x 512
__device__ __align__(16) uint32_t g_b3[2][2048];      // h3:  4 kb x 512

// ---------------- helpers ----------------
__device__ __forceinline__ void mma_bf16(float* c, const uint32_t* a, const uint32_t* b) {
    asm volatile(
        "mma.sync.aligned.m16n8k16.row.col.f32.bf16.bf16.f32 "
        "{%0,%1,%2,%3}, {%4,%5,%6,%7}, {%8,%9}, {%0,%1,%2,%3};"
        : "+f"(c[0]), "+f"(c[1]), "+f"(c[2]), "+f"(c[3])
        : "r"(a[0]), "r"(a[1]), "r"(a[2]), "r"(a[3]), "r"(b[0]), "r"(b[1]));
}

__device__ __forceinline__ void mma_f16(float* c, const uint32_t* a, const uint32_t* b) {
    asm volatile(
        "mma.sync.aligned.m16n8k16.row.col.f32.f16.f16.f32 "
        "{%0,%1,%2,%3}, {%4,%5,%6,%7}, {%8,%9}, {%0,%1,%2,%3};"
        : "+f"(c[0]), "+f"(c[1]), "+f"(c[2]), "+f"(c[3])
        : "r"(a[0]), "r"(a[1]), "r"(a[2]), "r"(a[3]), "r"(b[0]), "r"(b[1]));
}

__device__ __forceinline__ void ldsm_x4(uint32_t* r, uint32_t addr) {
    asm volatile("ldmatrix.sync.aligned.m8n8.x4.shared.b16 {%0,%1,%2,%3}, [%4];"
                 : "=r"(r[0]), "=r"(r[1]), "=r"(r[2]), "=r"(r[3]) : "r"(addr));
}

__device__ __forceinline__ void cp_async16(uint32_t smem, const void* g) {
    asm volatile("cp.async.cg.shared.global [%0], [%1], 16;" :: "r"(smem), "l"(g));
}

__device__ __forceinline__ float rcp_(float x) {
    float r;
    asm("rcp.approx.f32 %0, %1;" : "=f"(r) : "f"(x));
    return r;
}
__device__ __forceinline__ float fast_sig(float x) { return rcp_(1.0f + __expf(-x)); }
__device__ __forceinline__ float fast_tanh(float x) { return 2.0f * rcp_(1.0f + __expf(-2.0f * x)) - 1.0f; }

__device__ __forceinline__ uint32_t pack_h2(float a, float b) {
    __half2 h = __floats2half2_rn(a, b);
    return *reinterpret_cast<uint32_t*>(&h);
}

// ---------------- fp32 -> bf16 conversion (vectorized) ----------------
__global__ void f2bf_kernel(const float* __restrict__ src, __nv_bfloat16* __restrict__ dst, int n4) {
    const int stride = gridDim.x * blockDim.x;
    __nv_bfloat162* d2 = (__nv_bfloat162*)dst;
    for (int i = blockIdx.x * blockDim.x + threadIdx.x; i < n4; i += stride) {
        const float4 v = ((const float4*)src)[i];
        d2[2 * i]     = __floats2bfloat162_rn(v.x, v.y);
        d2[2 * i + 1] = __floats2bfloat162_rn(v.z, v.w);
    }
}

// ---------------- bf16 GEMM (512 threads, 16 warps, 4-stage cp.async) ----------------
__global__ __launch_bounds__(512, 1) void gemm_bf16_bias(
    const __nv_bfloat16* __restrict__ A, const __nv_bfloat16* __restrict__ Bw,
    const float* __restrict__ b1, const float* __restrict__ b2,
    float* __restrict__ C, int M, int N, int K)
{
    constexpr int BM = 128, BN = 128, BK = 32;
    constexpr int LDA = BK + 8;
    constexpr int ST  = 4;
    extern __shared__ __nv_bfloat16 gsm[];
    __nv_bfloat16* As = gsm;
    __nv_bfloat16* Bs = gsm + ST * BM * LDA;

    const int tid  = threadIdx.x;
    const int lane = tid & 31;
    const int warp = tid >> 5;     // 0..15
    const int wm   = warp & 3;
    const int wn   = warp >> 2;    // 0..3

    const long bm = (long)blockIdx.y * BM;
    const long bn = (long)blockIdx.x * BN;

    const uint32_t aBase = (uint32_t)__cvta_generic_to_shared(As);
    const uint32_t bBase = (uint32_t)__cvta_generic_to_shared(Bs);

    const int cr = tid >> 2;          // 0..127
    const int cs = (tid & 3) * 8;

    auto issue = [&](int st, int k0) {
        cp_async16(aBase + (uint32_t)(st * BM * LDA + cr * LDA + cs) * 2,
                   A + (size_t)(bm + cr) * K + k0 + cs);
        cp_async16(bBase + (uint32_t)(st * BN * LDA + cr * LDA + cs) * 2,
                   Bw + (size_t)(bn + cr) * K + k0 + cs);
    };

    const int KT = K / BK;

    issue(0, 0);
    asm volatile("cp.async.commit_group;");
    issue(1, BK);
    asm volatile("cp.async.commit_group;");
    issue(2, 2 * BK);
    asm volatile("cp.async.commit_group;");

    float acc[2][4][4];
#pragma unroll
    for (int mf = 0; mf < 2; ++mf)
#pragma unroll
        for (int nt = 0; nt < 4; ++nt)
#pragma unroll
            for (int q = 0; q < 4; ++q) acc[mf][nt][q] = 0.0f;

    const int aRow  = wm * 32 + (lane & 15);
    const int aColH = (lane >> 4) << 3;
    const int bRow  = wn * 32 + (((lane >> 4) & 1) << 3) + (lane & 7);
    const int bColH = ((lane >> 3) & 1) << 3;

    for (int kt = 0; kt < KT; ++kt) {
        asm volatile("cp.async.wait_group 2;");
        __syncthreads();
        if (kt + 3 < KT) issue((kt + 3) & (ST - 1), (kt + 3) * BK);
        asm volatile("cp.async.commit_group;");

        const int st = kt & (ST - 1);
        const uint32_t aS = aBase + (uint32_t)(st * BM * LDA) * 2;
        const uint32_t bS = bBase + (uint32_t)(st * BN * LDA) * 2;

#pragma unroll
        for (int kf = 0; kf < 2; ++kf) {
            const int k0 = kf * 16;
            uint32_t afr[2][4];
#pragma unroll
            for (int mf = 0; mf < 2; ++mf)
                ldsm_x4(afr[mf], aS + (uint32_t)((aRow + mf * 16) * LDA + k0 + aColH) * 2);
            uint32_t bfr[2][4];
#pragma unroll
            for (int np = 0; np < 2; ++np)
                ldsm_x4(bfr[np], bS + (uint32_t)((bRow + np * 16) * LDA + k0 + bColH) * 2);
#pragma unroll
            for (int mf = 0; mf < 2; ++mf)
#pragma unroll
                for (int nt = 0; nt < 4; ++nt)
                    mma_bf16(acc[mf][nt], afr[mf], &bfr[nt >> 1][(nt & 1) * 2]);
        }
    }

#pragma unroll
    for (int mf = 0; mf < 2; ++mf) {
#pragma unroll
        for (int nt = 0; nt < 4; ++nt) {
            const long r0 = bm + wm * 32 + mf * 16 + (lane >> 2);
            const long c0 = bn + wn * 32 + nt * 8 + 2 * (lane & 3);
            const float bias0 = b1[c0] + b2[c0];
            const float bias1 = b1[c0 + 1] + b2[c0 + 1];
            C[r0 * N + c0]           = acc[mf][nt][0] + bias0;
            C[r0 * N + c0 + 1]       = acc[mf][nt][1] + bias1;
            C[(r0 + 8) * N + c0]     = acc[mf][nt][2] + bias0;
            C[(r0 + 8) * N + c0 + 1] = acc[mf][nt][3] + bias1;
        }
    }
}

// ---------------- 16-CTA-cluster fused 3-layer LSTM ----------------
// Each CTA owns: L1 16 h-units (64 gate cols), L2 8 (32 cols), L3 4 (16 cols).
// Per step: stage h1(s-1)/h2(s-2)/h3(s-3) frags via cp.async, mma all roles,
// activations, write own h slices, barrier.cluster.
__global__ __launch_bounds__(512, 1) void lstm_cluster(
    const float* __restrict__ xg,
    const float* __restrict__ Whh1,
    const float* __restrict__ Wih2, const float* __restrict__ Whh2,
    const float* __restrict__ bih2, const float* __restrict__ bhh2,
    const float* __restrict__ Wih3, const float* __restrict__ Whh3,
    const float* __restrict__ bih3, const float* __restrict__ bhh3,
    float* __restrict__ hlast)
{
    extern __shared__ char smem[];
    // SMEM layout (bytes):
    uint32_t* Ah1 = (uint32_t*)smem;                    // 8192 u32 (32KB)  h1 frags
    uint32_t* Ah2 = Ah1 + 8192;                         // 4096 u32 (16KB)  h2 frags
    uint32_t* Ah3 = Ah2 + 4096;                         // 2048 u32 (8KB)   h3 frags
    float* gS1 = (float*)(Ah3 + 2048);                  // 2 slabs * 64 * 66
    float* gS2 = gS1 + 2 * 64 * 66;                     // 4 slabs * 64 * 34
    float* gS3 = gS2 + 4 * 64 * 34;                     // 6 slabs * 64 * 18
    uint32_t* hS1 = (uint32_t*)(gS3 + 6 * 64 * 18);     // 512 u32
    uint32_t* hS2 = hS1 + 512;                          // 256 u32
    uint32_t* hS3 = hS2 + 256;                          // 128 u32

    const int tid  = threadIdx.x;
    const int lane = tid & 31;
    const int w    = tid >> 5;          // 0..15
    const int grp  = lane >> 2;
    const int th4  = lane & 3;
    const int rank = blockIdx.x;        // 0..15

    const uint32_t Ah1B = (uint32_t)__cvta_generic_to_shared(Ah1);
    const uint32_t Ah2B = (uint32_t)__cvta_generic_to_shared(Ah2);
    const uint32_t Ah3B = (uint32_t)__cvta_generic_to_shared(Ah3);

    // ==== build weight B fragments in registers (once) ====
    // L1: nt1 = w&7 (8 n-tiles), ks1 = w>>3 (2 k-slices of 8 kb)
    const int nt1 = w & 7, ks1 = w >> 3;
    uint32_t bw1[8][2];
    {
        const int n = nt1 * 8 + (lane >> 2);
        const int g = n >> 4, u = n & 15;
        const float* wr = Whh1 + (size_t)(g * H1C + rank * 16 + u) * H1C;
#pragma unroll
        for (int q = 0; q < 8; ++q) {
            const int kb = ks1 * 8 + q;
#pragma unroll
            for (int j = 0; j < 2; ++j) {
                const int k = kb * 16 + (lane & 3) * 2 + j * 8;
                bw1[q][j] = pack_h2(wr[k], wr[k + 1]);
            }
        }
    }
    // L2: nt2 = w&3 (4 n-tiles), ks2 = w>>2 (4 k-slices of 6 kb); kb<16: proj(h1), else rec(h2)
    const int nt2 = w & 3, ks2 = w >> 2;
    uint32_t bw2[6][2];
    {
        const int n = nt2 * 8 + (lane >> 2);
        const int g = n >> 3, u = n & 7;
        const int row = g * H2C + rank * 8 + u;
#pragma unroll
        for (int q = 0; q < 6; ++q) {
            const int kb = ks2 * 6 + q;
#pragma unroll
            for (int j = 0; j < 2; ++j) {
                const int k = kb * 16 + (lane & 3) * 2 + j * 8;
                float w0, w1;
                if (k < 256) { const float* p = Wih2 + (size_t)row * 256 + k; w0 = p[0]; w1 = p[1]; }
                else         { const float* p = Whh2 + (size_t)row * 128 + (k - 256); w0 = p[0]; w1 = p[1]; }
                bw2[q][j] = pack_h2(w0, w1);
            }
        }
    }
    // L3: warps 0..11: nt3 = w&1, ks3 = w>>1 (6 k-slices of 2 kb); kb<8: proj(h2), else rec(h3)
    const int nt3 = w & 1, ks3 = w >> 1;
    uint32_t bw3[2][2] = {{0u, 0u}, {0u, 0u}};
    if (w < 12) {
        const int n = nt3 * 8 + (lane >> 2);
        const int g = n >> 2, u = n & 3;
        const int row = g * H3C + rank * 4 + u;
#pragma unroll
        for (int q = 0; q < 2; ++q) {
            const int kb = ks3 * 2 + q;
#pragma unroll
            for (int j = 0; j < 2; ++j) {
                const int k = kb * 16 + (lane & 3) * 2 + j * 8;
                float w0, w1;
                if (k < 128) { const float* p = Wih3 + (size_t)row * 128 + k; w0 = p[0]; w1 = p[1]; }
                else         { const float* p = Whh3 + (size_t)row * 64 + (k - 128); w0 = p[0]; w1 = p[1]; }
                bw3[q][j] = pack_h2(w0, w1);
            }
        }
    }

    // ==== elementwise ownership + biases ====
    // L1: pairs p = tid, tid+512 -> (b, u16)
    const int b1a = tid >> 4;        // 0..31 (pair 0), +32 for pair 1
    const int u1  = tid & 15;
    // L2: (b2, u2) = (tid>>3, tid&7)
    const int b2 = tid >> 3, u2 = tid & 7;
    // L3: threads 0-255: (b3, u3) = (tid>>2, tid&3)
    const int b3 = tid >> 2, u3 = tid & 3;

    float bias2[4], bias3[4];
#pragma unroll
    for (int g = 0; g < 4; ++g) {
        const int r2 = g * H2C + rank * 8 + u2;
        bias2[g] = bih2[r2] + bhh2[r2];
    }
    if (tid < 256) {
#pragma unroll
        for (int g = 0; g < 4; ++g) {
            const int r3 = g * H3C + rank * 4 + u3;
            bias3[g] = bih3[r3] + bhh3[r3];
        }
    }

    float c1[2] = {0.f, 0.f}, c2v = 0.f, c3v = 0.f;

    // initial xg prefetch for t=0
    float xr[2][4];
#pragma unroll
    for (int pp = 0; pp < 2; ++pp) {
        const int b = b1a + pp * 32;
        const float* xp = xg + ((size_t)b * TT + 0) * 1024 + rank * 16 + u1;
#pragma unroll
        for (int g = 0; g < 4; ++g) xr[pp][g] = xp[g * 256];
    }

    const int mi_w = w & 3;   // generic mi helper not used; per-role loops below

    for (int s = 0; s < TOTS; ++s) {
        const int t1 = s, t2 = s - 1, t3 = s - 2;
        const bool a1 = (t1 < TT);
        const bool a2 = (t2 >= 0) && (t2 < TT);
        const bool a3 = (t3 >= 0) && (t3 < TT);

        // ---- stage h fragments via cp.async (L2-coherent) ----
        if (s >= 1 && s <= TT) {
            const uint32_t* src = g_b1[(s - 1) & 1];
#pragma unroll
            for (int i = 0; i < 4; ++i)
                cp_async16(Ah1B + (uint32_t)(tid + i * 512) * 16, src + (size_t)(tid + i * 512) * 4);
        }
        if (s >= 2 && s <= TT + 1) {
            const uint32_t* src = g_b2[s & 1];          // h2(s-2) -> buf[(s-2)&1] = buf[s&1]
#pragma unroll
            for (int i = 0; i < 2; ++i)
                cp_async16(Ah2B + (uint32_t)(tid + i * 512) * 16, src + (size_t)(tid + i * 512) * 4);
        }
        if (s >= 3 && s <= TT + 1) {
            const uint32_t* src = g_b3[(s - 3) & 1];
            cp_async16(Ah3B + (uint32_t)tid * 16, src + (size_t)tid * 4);
        }
        asm volatile("cp.async.commit_group;");
        asm volatile("cp.async.wait_group 0;");
        __syncthreads();

        // ---- mma phase ----
        if (t1 >= 1 && a1) {
#pragma unroll
            for (int mi = 0; mi < 4; ++mi) {
                float acc[4] = {0.f, 0.f, 0.f, 0.f};
#pragma unroll
                for (int q = 0; q < 8; ++q) {
                    const int kb = ks1 * 8 + q;
                    const float4 av = *(const float4*)(Ah1 + ((size_t)(kb * 4 + mi) * 32 + lane) * 4);
                    mma_f16(acc, (const uint32_t*)&av, bw1[q]);
                }
                float* gr = gS1 + ks1 * (64 * 66) + (mi * 16 + grp) * 66 + nt1 * 8 + 2 * th4;
                gr[0] = acc[0]; gr[1] = acc[1];
                gr[8 * 66] = acc[2]; gr[8 * 66 + 1] = acc[3];
            }
        }
        if (a2) {
#pragma unroll
            for (int mi = 0; mi < 4; ++mi) {
                float acc[4] = {0.f, 0.f, 0.f, 0.f};
#pragma unroll
                for (int q = 0; q < 6; ++q) {
                    const int kb = ks2 * 6 + q;
                    if (kb < 16) {
                        const float4 av = *(const float4*)(Ah1 + ((size_t)(kb * 4 + mi) * 32 + lane) * 4);
                        mma_f16(acc, (const uint32_t*)&av, bw2[q]);
                    } else if (t2 >= 1) {
                        const float4 av = *(const float4*)(Ah2 + ((size_t)((kb - 16) * 4 + mi) * 32 + lane) * 4);
                        mma_f16(acc, (const uint32_t*)&av, bw2[q]);
                    }
                }
                float* gr = gS2 + ks2 * (64 * 34) + (mi * 16 + grp) * 34 + nt2 * 8 + 2 * th4;
                gr[0] = acc[0]; gr[1] = acc[1];
                gr[8 * 34] = acc[2]; gr[8 * 34 + 1] = acc[3];
            }
        }
        if (a3 && w < 12) {
#pragma unroll
            for (int mi = 0; mi < 4; ++mi) {
                float acc[4] = {0.f, 0.f, 0.f, 0.f};
#pragma unroll
                for (int q = 0; q < 2; ++q) {
                    const int kb = ks3 * 2 + q;
                    if (kb < 8) {
                        const float4 av = *(const float4*)(Ah2 + ((size_t)(kb * 4 + mi) * 32 + lane) * 4);
                        mma_f16(acc, (const uint32_t*)&av, bw3[q]);
                    } else if (t3 >= 1) {
                        const float4 av = *(const float4*)(Ah3 + ((size_t)((kb - 8) * 4 + mi) * 32 + lane) * 4);
                        mma_f16(acc, (const uint32_t*)&av, bw3[q]);
                    }
                }
                float* gr = gS3 + ks3 * (64 * 18) + (mi * 16 + grp) * 18 + nt3 * 8 + 2 * th4;
                gr[0] = acc[0]; gr[1] = acc[1];
                gr[8 * 18] = acc[2]; gr[8 * 18 + 1] = acc[3];
            }
        }
        __syncthreads();

        // ---- activations ----
        if (a1) {
#pragma unroll
            for (int pp = 0; pp < 2; ++pp) {
                const int b = b1a + pp * 32;
                float pi = xr[pp][0], pf = xr[pp][1], pg = xr[pp][2], po = xr[pp][3];
                if (t1 > 0) {
#pragma unroll
                    for (int sl = 0; sl < 2; ++sl) {
                        const float* row = gS1 + sl * (64 * 66) + b * 66;
                        pi += row[u1]; pf += row[16 + u1]; pg += row[32 + u1]; po += row[48 + u1];
                    }
                }
                const float iv = fast_sig(pi), fv = fast_sig(pf);
                const float gv = fast_tanh(pg), ov = fast_sig(po);
                c1[pp] = fv * c1[pp] + iv * gv;
                const float h = ov * fast_tanh(c1[pp]);
                const int r = b & 15, mi = b >> 4;
                const int lw = (r & 7) * 4 + ((u1 & 7) >> 1);
                const int rg = ((u1 >> 3) << 1) | (r >> 3);
                ((__half*)hS1)[((mi * 32 + lw) * 4 + rg) * 2 + (u1 & 1)] = __float2half(h);
                // prefetch xg for t1+1
                if (t1 + 1 < TT) {
                    const float* xp = xg + ((size_t)b * TT + (t1 + 1)) * 1024 + rank * 16 + u1;
#pragma unroll
                    for (int g = 0; g < 4; ++g) xr[pp][g] = xp[g * 256];
                }
            }
        }
        if (a2) {
            float pi = bias2[0], pf = bias2[1], pg = bias2[2], po = bias2[3];
#pragma unroll
            for (int sl = 0; sl < 4; ++sl) {
                const float* row = gS2 + sl * (64 * 34) + b2 * 34;
                pi += row[u2]; pf += row[8 + u2]; pg += row[16 + u2]; po += row[24 + u2];
            }
            const float iv = fast_sig(pi), fv = fast_sig(pf);
            const float gv = fast_tanh(pg), ov = fast_sig(po);
            c2v = fv * c2v + iv * gv;
            const float h = ov * fast_tanh(c2v);
            const int r = b2 & 15, mi = b2 >> 4;
            const int lw = (r & 7) * 4 + (u2 >> 1);
            ((__half*)hS2)[(((mi * 32 + lw) * 2) + (r >> 3)) * 2 + (u2 & 1)] = __float2half(h);
        }
        if (a3 && tid < 256) {
            float pi = bias3[0], pf = bias3[1], pg = bias3[2], po = bias3[3];
#pragma unroll
            for (int sl = 0; sl < 6; ++sl) {
                const float* row = gS3 + sl * (64 * 18) + b3 * 18;
                pi += row[u3]; pf += row[4 + u3]; pg += row[8 + u3]; po += row[12 + u3];
            }
            const float iv = fast_sig(pi), fv = fast_sig(pf);
            const float gv = fast_tanh(pg), ov = fast_sig(po);
            c3v = fv * c3v + iv * gv;
            const float h = ov * fast_tanh(c3v);
            ((__half*)hS3)[b3 * 4 + u3] = __float2half(h);
            if (t3 == TT - 1) hlast[(size_t)b3 * H3C + rank * 4 + u3] = h;
        }
        __syncthreads();

        // ---- publish own h slices to global ping-pong buffers ----
        if (a1 && tid < 128) {
            ((uint4*)g_b1[t1 & 1])[rank * 128 + tid] = ((const uint4*)hS1)[tid];
        }
        if (a2 && tid >= 128 && tid < 256) {
            const int q = tid - 128;
            uint32_t* dst = g_b2[t2 & 1] +
                ((size_t)(((rank >> 1) * 4 + (q >> 5)) * 32 + (q & 31)) * 4 + (rank & 1) * 2);
            *(uint2*)dst = *(const uint2*)(hS2 + q * 2);
        }
        if (a3 && tid >= 256 && tid < 384) {
            const int j = tid - 256;
            const int mi = j >> 5, r = (j >> 1) & 15, ss = j & 1;
            const size_t gidx =
                ((size_t)(((rank >> 2) * 4 + mi) * 32 + (r & 7) * 4 + (rank & 1) * 2 + ss)) * 4 +
                ((rank >> 1) & 1) * 2 + (r >> 3);
            g_b3[t3 & 1][gidx] = hS3[(mi * 16 + r) * 2 + ss];
        }
        __syncthreads();

        // ---- cluster barrier (release/acquire across all 16 CTAs) ----
        asm volatile("barrier.cluster.arrive.aligned;" ::: "memory");
        asm volatile("barrier.cluster.wait.aligned;" ::: "memory");
    }
    (void)mi_w;
}

// ---------------- head: deep/wide/concat/output (256 threads) ----------------
__global__ __launch_bounds__(256) void head_kernel(
    const float* __restrict__ x,
    const float* __restrict__ h3last,
    const float* __restrict__ Wd, const float* __restrict__ bd,
    const float* __restrict__ Ww, const float* __restrict__ bw,
    const float* __restrict__ Wo, const float* __restrict__ bo,
    float* __restrict__ out)
{
    const int bidx = blockIdx.x;
    const int j = threadIdx.x & 31;
    const int s = threadIdx.x >> 5;
    __shared__ float red[8][33];

    const float* xrow = x + ((size_t)bidx * TT + (TT - 1)) * DD;
    const float* wwr = Ww + (size_t)j * DD;
    float acc = 0.0f;
    const int k0 = s * (DD / 8);
#pragma unroll 4
    for (int k = k0; k < k0 + DD / 8; k += 4) {
        const float4 xv = *(const float4*)&xrow[k];
        const float4 wv = *(const float4*)&wwr[k];
        acc = fmaf(xv.x, wv.x, acc);
        acc = fmaf(xv.y, wv.y, acc);
        acc = fmaf(xv.z, wv.z, acc);
        acc = fmaf(xv.w, wv.w, acc);
    }
    red[s][j] = acc;
    __syncthreads();

    if (s == 0) {
        float wide = bw[j];
#pragma unroll
        for (int q = 0; q < 8; ++q) wide += red[q][j];
        wide = fmaxf(wide, 0.0f);

        const float* hrow = h3last + (size_t)bidx * H3C;
        const float* wdr = Wd + (size_t)j * H3C;
        float deep = bd[j];
#pragma unroll
        for (int k = 0; k < H3C; ++k) deep = fmaf(hrow[k], wdr[k], deep);
        deep = fmaxf(deep, 0.0f);

        float v = deep * Wo[j] + wide * Wo[32 + j];
#pragma unroll
        for (int off = 16; off > 0; off >>= 1)
            v += __shfl_xor_sync(0xffffffffu, v, off);
        if (j == 0) out[bidx] = v + bo[0];
    }
}

// ---------------- launch ----------------
extern "C" void kernel_launch(void* const* d_in, const int* in_sizes, int n_in,
                              void* d_out, int out_size) {
    const float* x    = (const float*)d_in[0];
    const float* Wih1 = (const float*)d_in[1];
    const float* Whh1 = (const float*)d_in[2];
    const float* bih1 = (const float*)d_in[3];
    const float* bhh1 = (const float*)d_in[4];
    const float* Wih2 = (const float*)d_in[5];
    const float* Whh2 = (const float*)d_in[6];
    const float* bih2 = (const float*)d_in[7];
    const float* bhh2 = (const float*)d_in[8];
    const float* Wih3 = (const float*)d_in[9];
    const float* Whh3 = (const float*)d_in[10];
    const float* bih3 = (const float*)d_in[11];
    const float* bhh3 = (const float*)d_in[12];
    const float* Wd   = (const float*)d_in[13];
    const float* bd   = (const float*)d_in[14];
    const float* Ww   = (const float*)d_in[15];
    const float* bw   = (const float*)d_in[16];
    const float* Wo   = (const float*)d_in[17];
    const float* bo   = (const float*)d_in[18];
    float* out = (float*)d_out;

    float *xg1, *h3;
    __nv_bfloat16 *xbf, *W1bf;
    cudaGetSymbolAddress((void**)&xg1,  g_xg1);
    cudaGetSymbolAddress((void**)&h3,   g_h3);
    cudaGetSymbolAddress((void**)&xbf,  g_xbf);
    cudaGetSymbolAddress((void**)&W1bf, g_W1bf);

    const int M = BB * TT;  // 32768

    // convert x and Wih1 to bf16 for the big GEMM
    f2bf_kernel<<<4096, 256>>>(x,    xbf,  (BB * TT * DD) / 4);
    f2bf_kernel<<<512,  256>>>(Wih1, W1bf, (4 * H1C * DD) / 4);

    // layer-1 input projection: xg1 = x @ Wih1^T + bih1 + bhh1
    {
        const int gsmem = 4 * (128 + 128) * 40 * 2;  // 81920 B
        cudaFuncSetAttribute(gemm_bf16_bias, cudaFuncAttributeMaxDynamicSharedMemorySize, gsmem);
        dim3 grid((4 * H1C) / 128, M / 128);
        gemm_bf16_bias<<<grid, 512, gsmem>>>(xbf, W1bf, bih1, bhh1, xg1, M, 4 * H1C, DD);
    }

    // fused cluster recurrence
    {
        const int lsmem = (8192 + 4096 + 2048) * 4      // A frag staging
                        + (2 * 64 * 66 + 4 * 64 * 34 + 6 * 64 * 18) * 4   // gS slabs
                        + (512 + 256 + 128) * 4;        // hS
        cudaFuncSetAttribute(lstm_cluster, cudaFuncAttributeMaxDynamicSharedMemorySize, lsmem);
        cudaFuncSetAttribute(lstm_cluster, cudaFuncAttributeNonPortableClusterSizeAllowed, 1);

        cudaLaunchConfig_t cfg = {};
        cfg.gridDim = dim3(NCL, 1, 1);
        cfg.blockDim = dim3(512, 1, 1);
        cfg.dynamicSmemBytes = (size_t)lsmem;
        cfg.stream = 0;
        cudaLaunchAttribute attrs[1];
        attrs[0].id = cudaLaunchAttributeClusterDimension;
        attrs[0].val.clusterDim.x = NCL;
        attrs[0].val.clusterDim.y = 1;
        attrs[0].val.clusterDim.z = 1;
        cfg.attrs = attrs;
        cfg.numAttrs = 1;
        cudaLaunchKernelEx(&cfg, lstm_cluster, xg1, Whh1,
                           Wih2, Whh2, bih2, bhh2,
                           Wih3, Whh3, bih3, bhh3, h3);
    }

    // head
    head_kernel<<<BB, 256>>>(x, h3, Wd, bd, Ww, bw, Wo, bo, out);

    (void)in_sizes; (void)n_in; (void)out_size;
}

// round 8
// speedup vs baseline: 1.4757x; 1.4757x over previous
#include <cuda_runtime.h>
#include <cuda_bf16.h>
#include <cuda_fp16.h>
#include <cstdint>
#include <math.h>

// Problem dims (fixed by the reference)
#define BB 64
#define TT 512
#define DD 2048
#define H1 256
#define H2 128
#define H3 64

#define NCTA_ALL 36      // 16 (L1) + 16 (L2) + 4 (L3)
#define TOTS (TT + 2)

// ---------------- scratch (static device buffers; no allocation) ----------------
__device__ __align__(16) float g_xg1[(size_t)BB * TT * 4 * H1];   // 32768 x 1024
__device__ __align__(16) __nv_bfloat16 g_xbf[(size_t)BB * TT * DD];
__device__ __align__(16) __nv_bfloat16 g_W1bf[4 * H1 * DD];
__device__ __align__(16) float g_h3[BB * H3];         // layer-3 last h (fp32)
// h ping-pong fragment buffers (fp16 mma A-fragment layout, u32 units)
__device__ __align__(16) uint32_t g_b1[2][8192];      // h1: 16 kb x 512 u32
__device__ __align__(16) uint32_t g_b2[2][4096];      // h2:  8 kb x 512
__device__ __align__(16) uint32_t g_b3[2][2048];      // h3:  4 kb x 512
__device__ unsigned g_flags[NCTA_ALL * 32];           // one flag per CTA, 128B apart

// ---------------- helpers ----------------
__device__ __forceinline__ void mma_bf16(float* c, const uint32_t* a, const uint32_t* b) {
    asm volatile(
        "mma.sync.aligned.m16n8k16.row.col.f32.bf16.bf16.f32 "
        "{%0,%1,%2,%3}, {%4,%5,%6,%7}, {%8,%9}, {%0,%1,%2,%3};"
        : "+f"(c[0]), "+f"(c[1]), "+f"(c[2]), "+f"(c[3])
        : "r"(a[0]), "r"(a[1]), "r"(a[2]), "r"(a[3]), "r"(b[0]), "r"(b[1]));
}

__device__ __forceinline__ void mma_f16(float* c, const uint32_t* a, const uint32_t* b) {
    asm volatile(
        "mma.sync.aligned.m16n8k16.row.col.f32.f16.f16.f32 "
        "{%0,%1,%2,%3}, {%4,%5,%6,%7}, {%8,%9}, {%0,%1,%2,%3};"
        : "+f"(c[0]), "+f"(c[1]), "+f"(c[2]), "+f"(c[3])
        : "r"(a[0]), "r"(a[1]), "r"(a[2]), "r"(a[3]), "r"(b[0]), "r"(b[1]));
}

__device__ __forceinline__ void ldsm_x4(uint32_t* r, uint32_t addr) {
    asm volatile("ldmatrix.sync.aligned.m8n8.x4.shared.b16 {%0,%1,%2,%3}, [%4];"
                 : "=r"(r[0]), "=r"(r[1]), "=r"(r[2]), "=r"(r[3]) : "r"(addr));
}

__device__ __forceinline__ void cp_async16(uint32_t smem, const void* g) {
    asm volatile("cp.async.cg.shared.global [%0], [%1], 16;" :: "r"(smem), "l"(g));
}

__device__ __forceinline__ float rcp_(float x) {
    float r;
    asm("rcp.approx.f32 %0, %1;" : "=f"(r) : "f"(x));
    return r;
}
__device__ __forceinline__ float fast_sig(float x) { return rcp_(1.0f + __expf(-x)); }
__device__ __forceinline__ float fast_tanh(float x) { return 2.0f * rcp_(1.0f + __expf(-2.0f * x)) - 1.0f; }

__device__ __forceinline__ uint32_t pack_h2(float a, float b) {
    __half2 h = __floats2half2_rn(a, b);
    return *reinterpret_cast<uint32_t*>(&h);
}

// ---------------- prep: zero flags + h fragment buffers (every replay) ----------------
__global__ void prep_zero() {
    const int i = blockIdx.x * blockDim.x + threadIdx.x;
    if (i < NCTA_ALL * 32) g_flags[i] = 0u;
    const int n1 = 2 * 8192, n2 = 2 * 4096, n3 = 2 * 2048;
    uint32_t* p1 = (uint32_t*)g_b1;
    uint32_t* p2 = (uint32_t*)g_b2;
    uint32_t* p3 = (uint32_t*)g_b3;
    const int stride = gridDim.x * blockDim.x;
    for (int k = i; k < n1; k += stride) p1[k] = 0u;
    for (int k = i; k < n2; k += stride) p2[k] = 0u;
    for (int k = i; k < n3; k += stride) p3[k] = 0u;
}

// ---------------- fp32 -> bf16 conversion (vectorized) ----------------
__global__ void f2bf_kernel(const float* __restrict__ src, __nv_bfloat16* __restrict__ dst, int n4) {
    const int stride = gridDim.x * blockDim.x;
    __nv_bfloat162* d2 = (__nv_bfloat162*)dst;
    for (int i = blockIdx.x * blockDim.x + threadIdx.x; i < n4; i += stride) {
        const float4 v = ((const float4*)src)[i];
        d2[2 * i]     = __floats2bfloat162_rn(v.x, v.y);
        d2[2 * i + 1] = __floats2bfloat162_rn(v.z, v.w);
    }
}

// ---------------- bf16 GEMM (512 threads, 16 warps, 4-stage cp.async) ----------------
__global__ __launch_bounds__(512, 1) void gemm_bf16_bias(
    const __nv_bfloat16* __restrict__ A, const __nv_bfloat16* __restrict__ Bw,
    const float* __restrict__ b1, const float* __restrict__ b2,
    float* __restrict__ C, int M, int N, int K)
{
    constexpr int BM = 128, BN = 128, BK = 32;
    constexpr int LDA = BK + 8;
    constexpr int ST  = 4;
    extern __shared__ __nv_bfloat16 gsm[];
    __nv_bfloat16* As = gsm;
    __nv_bfloat16* Bs = gsm + ST * BM * LDA;

    const int tid  = threadIdx.x;
    const int lane = tid & 31;
    const int warp = tid >> 5;     // 0..15
    const int wm   = warp & 3;
    const int wn   = warp >> 2;    // 0..3

    const long bm = (long)blockIdx.y * BM;
    const long bn = (long)blockIdx.x * BN;

    const uint32_t aBase = (uint32_t)__cvta_generic_to_shared(As);
    const uint32_t bBase = (uint32_t)__cvta_generic_to_shared(Bs);

    const int cr = tid >> 2;          // 0..127
    const int cs = (tid & 3) * 8;

    auto issue = [&](int st, int k0) {
        cp_async16(aBase + (uint32_t)(st * BM * LDA + cr * LDA + cs) * 2,
                   A + (size_t)(bm + cr) * K + k0 + cs);
        cp_async16(bBase + (uint32_t)(st * BN * LDA + cr * LDA + cs) * 2,
                   Bw + (size_t)(bn + cr) * K + k0 + cs);
    };

    const int KT = K / BK;

    issue(0, 0);
    asm volatile("cp.async.commit_group;");
    issue(1, BK);
    asm volatile("cp.async.commit_group;");
    issue(2, 2 * BK);
    asm volatile("cp.async.commit_group;");

    float acc[2][4][4];
#pragma unroll
    for (int mf = 0; mf < 2; ++mf)
#pragma unroll
        for (int nt = 0; nt < 4; ++nt)
#pragma unroll
            for (int q = 0; q < 4; ++q) acc[mf][nt][q] = 0.0f;

    const int aRow  = wm * 32 + (lane & 15);
    const int aColH = (lane >> 4) << 3;
    const int bRow  = wn * 32 + (((lane >> 4) & 1) << 3) + (lane & 7);
    const int bColH = ((lane >> 3) & 1) << 3;

    for (int kt = 0; kt < KT; ++kt) {
        asm volatile("cp.async.wait_group 2;");
        __syncthreads();
        if (kt + 3 < KT) issue((kt + 3) & (ST - 1), (kt + 3) * BK);
        asm volatile("cp.async.commit_group;");

        const int st = kt & (ST - 1);
        const uint32_t aS = aBase + (uint32_t)(st * BM * LDA) * 2;
        const uint32_t bS = bBase + (uint32_t)(st * BN * LDA) * 2;

#pragma unroll
        for (int kf = 0; kf < 2; ++kf) {
            const int k0 = kf * 16;
            uint32_t afr[2][4];
#pragma unroll
            for (int mf = 0; mf < 2; ++mf)
                ldsm_x4(afr[mf], aS + (uint32_t)((aRow + mf * 16) * LDA + k0 + aColH) * 2);
            uint32_t bfr[2][4];
#pragma unroll
            for (int np = 0; np < 2; ++np)
                ldsm_x4(bfr[np], bS + (uint32_t)((bRow + np * 16) * LDA + k0 + bColH) * 2);
#pragma unroll
            for (int mf = 0; mf < 2; ++mf)
#pragma unroll
                for (int nt = 0; nt < 4; ++nt)
                    mma_bf16(acc[mf][nt], afr[mf], &bfr[nt >> 1][(nt & 1) * 2]);
        }
    }

#pragma unroll
    for (int mf = 0; mf < 2; ++mf) {
#pragma unroll
        for (int nt = 0; nt < 4; ++nt) {
            const long r0 = bm + wm * 32 + mf * 16 + (lane >> 2);
            const long c0 = bn + wn * 32 + nt * 8 + 2 * (lane & 3);
            const float bias0 = b1[c0] + b2[c0];
            const float bias1 = b1[c0 + 1] + b2[c0 + 1];
            C[r0 * N + c0]           = acc[mf][nt][0] + bias0;
            C[r0 * N + c0 + 1]       = acc[mf][nt][1] + bias1;
            C[(r0 + 8) * N + c0]     = acc[mf][nt][2] + bias0;
            C[(r0 + 8) * N + c0 + 1] = acc[mf][nt][3] + bias1;
        }
    }
}

// ---------------- fused 3-layer pipelined LSTM (fp16 mma, weights in registers) -------
// Generalized role: H hidden, KP proj input (0 => xg in gmem), HC units per CTA.
// 512 threads, 16 warps = 4(mi) x KSN(k-slices) x NTG(n-groups); B frags in registers.
template <int H, int KP, int HC, int FIRST, bool LAST_ONLY>
__device__ __forceinline__ void lstm_role(
    char* dyn,
    const float* __restrict__ xg,
    const float* __restrict__ Wih,
    const float* __restrict__ Whh,
    const float* __restrict__ bih,
    const float* __restrict__ bhh,
    const uint32_t* __restrict__ bufP0, const uint32_t* __restrict__ bufP1,
    uint32_t* __restrict__ bufR0, uint32_t* __restrict__ bufR1,
    float* __restrict__ hlast,
    unsigned* __restrict__ flags,
    int ctaLocal, int myflag)
{
    constexpr int COLS = 4 * HC;
    constexpr int GSW  = COLS + 2;
    constexpr int NT   = COLS / 8;            // n-tiles of 8
    constexpr int NTG  = NT / 4;              // n-groups (warp covers 4 nt)
    constexpr int KSN  = 4 / NTG;             // k-slice count
    constexpr int KB_P = (KP > 0) ? KP / 16 : 0;
    constexpr int KBT  = KB_P + H / 16;       // total k16 blocks
    constexpr int KS   = KBT / KSN;           // kbs per warp
    constexpr int EPT  = HC / 8;              // elements per thread (1 or 2)
    constexpr int HSU  = 32 * HC;             // hS u32 count (CTA's fragment slice)
    static_assert(KS * KSN == KBT, "k split");
    static_assert(NTG * 4 == NT, "n split");

    uint32_t* Af  = (uint32_t*)dyn;                          // KBT*512 u32 staged A frags
    float*    gS  = (float*)(dyn + KBT * 2048);              // KSN slabs * 64 * GSW
    uint32_t* hS  = (uint32_t*)(gS + KSN * 64 * GSW);        // HSU u32

    const int tid  = threadIdx.x;
    const int lane = tid & 31;
    const int w    = tid >> 5;
    const int grp  = lane >> 2;
    const int th4  = lane & 3;
    const int h0   = ctaLocal * HC;

    const uint32_t AfB = (uint32_t)__cvta_generic_to_shared(Af);

    // ---- warp decomposition ----
    const int mi    = w & 3;
    const int wr    = w >> 2;               // 0..3
    const int ks    = wr & (KSN - 1);
    const int ntg_i = wr / KSN;

    // ---- build weight B fragments in registers (once) ----
    uint32_t bw[KS][4][2];
    {
        const int colb = lane >> 2;          // 0..7
        const int kk0  = (lane & 3) * 2;
#pragma unroll
        for (int q = 0; q < KS; ++q) {
            const int kbg = ks * KS + q;
#pragma unroll
            for (int nip = 0; nip < 4; ++nip) {
                const int c = (ntg_i * 4 + nip) * 8 + colb;   // 0..COLS-1
                const int g = c / HC, u = c % HC;
                const int row = g * H + h0 + u;
#pragma unroll
                for (int j = 0; j < 2; ++j) {
                    const int k = kbg * 16 + kk0 + j * 8;
                    float w0, w1;
                    if (KP > 0 && k < KP) {
                        const float* p = Wih + (size_t)row * KP + k;
                        w0 = p[0]; w1 = p[1];
                    } else {
                        const float* p = Whh + (size_t)row * H + (k - KP);
                        w0 = p[0]; w1 = p[1];
                    }
                    bw[q][nip][j] = pack_h2(w0, w1);
                }
            }
        }
    }

    // ---- elementwise ownership: thread -> (batch b, EPT units) ----
    const int b  = tid >> 3;                 // 0..63
    const int j0 = (tid & 7) * EPT;          // first unit index

    float cst[EPT];
    float xr[EPT][4];
    float bias[EPT][4];
#pragma unroll
    for (int e = 0; e < EPT; ++e) {
        cst[e] = 0.0f;
        const int kme = h0 + j0 + e;
        if (KP == 0) {
            const float* xp = xg + ((size_t)b * TT) * (4 * H) + kme;
#pragma unroll
            for (int g = 0; g < 4; ++g) xr[e][g] = xp[(size_t)g * H];
        } else {
#pragma unroll
            for (int g = 0; g < 4; ++g) {
                const int r = g * H + kme;
                bias[e][g] = bih[r] + bhh[r];
            }
        }
    }
    __syncthreads();

    for (int s = 0; s < TOTS; ++s) {
        const int t = s - FIRST;
        const bool active = (t >= 0) && (t < TT);

        // ---- stage A fragments via cp.async (proj h(t) then rec h(t-1)) ----
        if (active) {
            const uint32_t* srcP = (KP > 0) ? ((t & 1) ? bufP1 : bufP0) : (const uint32_t*)0;
            const uint32_t* srcR = (t & 1) ? bufR0 : bufR1;   // parity (t-1)&1
#pragma unroll
            for (int i = tid; i < KBT * 128; i += 512) {
                const uint32_t* src = (KP > 0 && i < KB_P * 128)
                                          ? (srcP + (size_t)i * 4)
                                          : (srcR + (size_t)(i - KB_P * 128) * 4);
                cp_async16(AfB + (uint32_t)i * 16, src);
            }
            asm volatile("cp.async.commit_group;");
            asm volatile("cp.async.wait_group 0;");
        }
        __syncthreads();

        // ---- mma: warp (mi, ks, ntg) covers 4 n-tiles over KS k-blocks ----
        if (active) {
            float acc[4][4];
#pragma unroll
            for (int nip = 0; nip < 4; ++nip)
#pragma unroll
                for (int q = 0; q < 4; ++q) acc[nip][q] = 0.0f;

#pragma unroll
            for (int q = 0; q < KS; ++q) {
                const int kb = ks * KS + q;
                const float4 av = *(const float4*)(Af + ((size_t)(kb * 4 + mi) * 32 + lane) * 4);
                const uint32_t* au = (const uint32_t*)&av;
#pragma unroll
                for (int nip = 0; nip < 4; ++nip)
                    mma_f16(acc[nip], au, bw[q][nip]);
            }

            float* gr = gS + ks * (64 * GSW) + (mi * 16 + grp) * GSW + 2 * th4;
#pragma unroll
            for (int nip = 0; nip < 4; ++nip) {
                const int cc = (ntg_i * 4 + nip) * 8;
                gr[cc]               = acc[nip][0];
                gr[cc + 1]           = acc[nip][1];
                gr[8 * GSW + cc]     = acc[nip][2];
                gr[8 * GSW + cc + 1] = acc[nip][3];
            }
        }
        __syncthreads();

        // ---- activations ----
        if (active) {
#pragma unroll
            for (int e = 0; e < EPT; ++e) {
                const int jj  = j0 + e;
                const int kme = h0 + jj;
                float pi, pf, pg, po;
                if (KP == 0) { pi = xr[e][0]; pf = xr[e][1]; pg = xr[e][2]; po = xr[e][3]; }
                else         { pi = bias[e][0]; pf = bias[e][1]; pg = bias[e][2]; po = bias[e][3]; }
#pragma unroll
                for (int sl = 0; sl < KSN; ++sl) {
                    const float* row = gS + sl * (64 * GSW) + b * GSW;
                    pi += row[jj];
                    pf += row[HC + jj];
                    pg += row[2 * HC + jj];
                    po += row[3 * HC + jj];
                }
                const float iv = fast_sig(pi), fv = fast_sig(pf);
                const float gv = fast_tanh(pg), ov = fast_sig(po);
                cst[e] = fv * cst[e] + iv * gv;
                const float h = ov * fast_tanh(cst[e]);

                // local fragment slice write (2B half)
                const int mib   = b >> 4;
                const int lanew = (b & 7) * 4 + ((jj & 7) >> 1);
                const int compl_ = (HC == 16)
                                       ? (((jj >> 3) & 1) * 2 + ((b >> 3) & 1))
                                       : ((b >> 3) & 1);
                const int compw = (HC == 16) ? 4 : 2;
                ((__half*)hS)[((mib * 32 + lanew) * compw + compl_) * 2 + (jj & 1)] = __float2half(h);

                if (LAST_ONLY && t == TT - 1)
                    hlast[(size_t)b * H + kme] = h;

                if (KP == 0 && t + 1 < TT) {
                    const float* xp = xg + ((size_t)b * TT + (t + 1)) * (4 * H) + kme;
#pragma unroll
                    for (int g = 0; g < 4; ++g) xr[e][g] = xp[(size_t)g * H];
                }
            }
        }
        __syncthreads();

        // ---- publish own h slice to global ping-pong buffer ----
        if (active) {
            uint32_t* gdst = (t & 1) ? bufR1 : bufR0;
            if (HC == 16) {
                if (tid < HSU / 4)
                    ((uint4*)(gdst + (size_t)ctaLocal * 512))[tid] = ((const uint4*)hS)[tid];
            } else {
                if (tid < HSU / 2) {
                    const int q = tid;       // (mi, lane) packed
                    uint32_t* dst = gdst + ((size_t)(ctaLocal >> 1) * 512)
                                    + ((size_t)((q >> 5) * 32 + (q & 31))) * 4
                                    + (ctaLocal & 1) * 2;
                    *(uint2*)dst = ((const uint2*)hS)[q];
                }
            }
        }
        __syncthreads();

        // ---- distributed flag barrier (all NCTA_ALL CTAs, every step) ----
        if (tid == 0) {
            asm volatile("st.release.gpu.global.u32 [%0], %1;"
                         :: "l"(flags + myflag * 32), "r"((unsigned)(s + 1)) : "memory");
        }
        if (tid < NCTA_ALL) {
            unsigned v;
            const unsigned tgt = (unsigned)(s + 1);
            unsigned* fp = flags + tid * 32;
            do {
                asm volatile("ld.acquire.gpu.global.u32 %0, [%1];" : "=r"(v) : "l"(fp) : "memory");
            } while (v < tgt);
        }
        __syncthreads();
    }
}

__global__ __launch_bounds__(512, 1) void lstm_fused(
    const float* __restrict__ xg1,
    const float* __restrict__ Whh1,
    const float* __restrict__ Wih2, const float* __restrict__ Whh2,
    const float* __restrict__ bih2, const float* __restrict__ bhh2,
    const float* __restrict__ Wih3, const float* __restrict__ Whh3,
    const float* __restrict__ bih3, const float* __restrict__ bhh3,
    float* __restrict__ h3out, unsigned* __restrict__ flags)
{
    extern __shared__ char dynls[];
    const int cb = blockIdx.x;
    if (cb < 16) {
        lstm_role<H1, 0, 16, 0, false>(dynls, xg1, nullptr, Whh1, nullptr, nullptr,
                                       nullptr, nullptr, g_b1[0], g_b1[1], nullptr,
                                       flags, cb, cb);
    } else if (cb < 32) {
        lstm_role<H2, H1, 8, 1, false>(dynls, nullptr, Wih2, Whh2, bih2, bhh2,
                                       g_b1[0], g_b1[1], g_b2[0], g_b2[1], nullptr,
                                       flags, cb - 16, cb);
    } else {
        lstm_role<H3, H2, 16, 2, true>(dynls, nullptr, Wih3, Whh3, bih3, bhh3,
                                       g_b2[0], g_b2[1], g_b3[0], g_b3[1], h3out,
                                       flags, cb - 32, cb);
    }
}

// ---------------- head: deep/wide/concat/output (256 threads) ----------------
__global__ __launch_bounds__(256) void head_kernel(
    const float* __restrict__ x,
    const float* __restrict__ h3last,
    const float* __restrict__ Wd, const float* __restrict__ bd,
    const float* __restrict__ Ww, const float* __restrict__ bw,
    const float* __restrict__ Wo, const float* __restrict__ bo,
    float* __restrict__ out)
{
    const int bidx = blockIdx.x;
    const int j = threadIdx.x & 31;
    const int s = threadIdx.x >> 5;
    __shared__ float red[8][33];

    const float* xrow = x + ((size_t)bidx * TT + (TT - 1)) * DD;
    const float* wwr = Ww + (size_t)j * DD;
    float acc = 0.0f;
    const int k0 = s * (DD / 8);
#pragma unroll 4
    for (int k = k0; k < k0 + DD / 8; k += 4) {
        const float4 xv = *(const float4*)&xrow[k];
        const float4 wv = *(const float4*)&wwr[k];
        acc = fmaf(xv.x, wv.x, acc);
        acc = fmaf(xv.y, wv.y, acc);
        acc = fmaf(xv.z, wv.z, acc);
        acc = fmaf(xv.w, wv.w, acc);
    }
    red[s][j] = acc;
    __syncthreads();

    if (s == 0) {
        float wide = bw[j];
#pragma unroll
        for (int q = 0; q < 8; ++q) wide += red[q][j];
        wide = fmaxf(wide, 0.0f);

        const float* hrow = h3last + (size_t)bidx * H3;
        const float* wdr = Wd + (size_t)j * H3;
        float deep = bd[j];
#pragma unroll
        for (int k = 0; k < H3; ++k) deep = fmaf(hrow[k], wdr[k], deep);
        deep = fmaxf(deep, 0.0f);

        float v = deep * Wo[j] + wide * Wo[32 + j];
#pragma unroll
        for (int off = 16; off > 0; off >>= 1)
            v += __shfl_xor_sync(0xffffffffu, v, off);
        if (j == 0) out[bidx] = v + bo[0];
    }
}

// ---------------- launch ----------------
extern "C" void kernel_launch(void* const* d_in, const int* in_sizes, int n_in,
                              void* d_out, int out_size) {
    const float* x    = (const float*)d_in[0];
    const float* Wih1 = (const float*)d_in[1];
    const float* Whh1 = (const float*)d_in[2];
    const float* bih1 = (const float*)d_in[3];
    const float* bhh1 = (const float*)d_in[4];
    const float* Wih2 = (const float*)d_in[5];
    const float* Whh2 = (const float*)d_in[6];
    const float* bih2 = (const float*)d_in[7];
    const float* bhh2 = (const float*)d_in[8];
    const float* Wih3 = (const float*)d_in[9];
    const float* Whh3 = (const float*)d_in[10];
    const float* bih3 = (const float*)d_in[11];
    const float* bhh3 = (const float*)d_in[12];
    const float* Wd   = (const float*)d_in[13];
    const float* bd   = (const float*)d_in[14];
    const float* Ww   = (const float*)d_in[15];
    const float* bw   = (const float*)d_in[16];
    const float* Wo   = (const float*)d_in[17];
    const float* bo   = (const float*)d_in[18];
    float* out = (float*)d_out;

    float *xg1, *h3;
    __nv_bfloat16 *xbf, *W1bf;
    unsigned* flags;
    cudaGetSymbolAddress((void**)&xg1,   g_xg1);
    cudaGetSymbolAddress((void**)&h3,    g_h3);
    cudaGetSymbolAddress((void**)&xbf,   g_xbf);
    cudaGetSymbolAddress((void**)&W1bf,  g_W1bf);
    cudaGetSymbolAddress((void**)&flags, g_flags);

    const int M = BB * TT;  // 32768

    prep_zero<<<60, 512>>>();

    // convert x and Wih1 to bf16 for the big GEMM
    f2bf_kernel<<<4096, 256>>>(x,    xbf,  (BB * TT * DD) / 4);
    f2bf_kernel<<<512,  256>>>(Wih1, W1bf, (4 * H1 * DD) / 4);

    // layer-1 input projection: xg1 = x @ Wih1^T + bih1 + bhh1
    {
        const int gsmem = 4 * (128 + 128) * 40 * 2;  // 81920 B
        cudaFuncSetAttribute(gemm_bf16_bias, cudaFuncAttributeMaxDynamicSharedMemorySize, gsmem);
        dim3 grid((4 * H1) / 128, M / 128);
        gemm_bf16_bias<<<grid, 512, gsmem>>>(xbf, W1bf, bih1, bhh1, xg1, M, 4 * H1, DD);
    }

    // fused pipelined 3-layer recurrence (36 CTAs, distributed flag barrier)
    {
        // max over roles: L2 = 24*2048 + 4*64*34*4 + 256*4 = 84992 B
        const int dynBytes = 84992;
        cudaFuncSetAttribute(lstm_fused, cudaFuncAttributeMaxDynamicSharedMemorySize, dynBytes);
        lstm_fused<<<NCTA_ALL, 512, dynBytes>>>(xg1, Whh1,
                                                Wih2, Whh2, bih2, bhh2,
                                                Wih3, Whh3, bih3, bhh3,
                                                h3, flags);
    }

    // head
    head_kernel<<<BB, 256>>>(x, h3, Wd, bd, Ww, bw, Wo, bo, out);

    (void)in_sizes; (void)n_in; (void)out_size;
}

// round 9
// speedup vs baseline: 1.5324x; 1.0385x over previous
#include <cuda_runtime.h>
#include <cuda_bf16.h>
#include <cuda_fp16.h>
#include <cstdint>
#include <math.h>

// Problem dims (fixed by the reference)
#define BB 64
#define TT 512
#define DD 2048
#define H1 256
#define H2 128
#define H3 64

#define NCTA_ALL 36      // 16 (L1) + 16 (L2) + 4 (L3)
#define TOTS (TT + 2)

// ---------------- scratch (static device buffers; no allocation) ----------------
__device__ __align__(16) float g_xg1[(size_t)BB * TT * 4 * H1];   // 32768 x 1024
__device__ __align__(16) __nv_bfloat16 g_xbf[(size_t)BB * TT * DD];
__device__ __align__(16) __nv_bfloat16 g_W1bf[4 * H1 * DD];
__device__ __align__(16) float g_h3[BB * H3];         // layer-3 last h (fp32)
// h ping-pong fragment buffers (fp16 mma A-fragment layout, u32 units)
__device__ __align__(16) uint32_t g_b1[2][8192];      // h1: 16 kb x 512 u32
__device__ __align__(16) uint32_t g_b2[2][4096];      // h2:  8 kb x 512
__device__ __align__(16) uint32_t g_b3[2][2048];      // h3:  4 kb x 512
__device__ unsigned g_flags[NCTA_ALL * 32];           // one flag per CTA, 128B apart

// ---------------- helpers ----------------
__device__ __forceinline__ void mma_bf16(float* c, const uint32_t* a, const uint32_t* b) {
    asm volatile(
        "mma.sync.aligned.m16n8k16.row.col.f32.bf16.bf16.f32 "
        "{%0,%1,%2,%3}, {%4,%5,%6,%7}, {%8,%9}, {%0,%1,%2,%3};"
        : "+f"(c[0]), "+f"(c[1]), "+f"(c[2]), "+f"(c[3])
        : "r"(a[0]), "r"(a[1]), "r"(a[2]), "r"(a[3]), "r"(b[0]), "r"(b[1]));
}

__device__ __forceinline__ void mma_f16(float* c, const uint32_t* a, const uint32_t* b) {
    asm volatile(
        "mma.sync.aligned.m16n8k16.row.col.f32.f16.f16.f32 "
        "{%0,%1,%2,%3}, {%4,%5,%6,%7}, {%8,%9}, {%0,%1,%2,%3};"
        : "+f"(c[0]), "+f"(c[1]), "+f"(c[2]), "+f"(c[3])
        : "r"(a[0]), "r"(a[1]), "r"(a[2]), "r"(a[3]), "r"(b[0]), "r"(b[1]));
}

__device__ __forceinline__ void ldsm_x4(uint32_t* r, uint32_t addr) {
    asm volatile("ldmatrix.sync.aligned.m8n8.x4.shared.b16 {%0,%1,%2,%3}, [%4];"
                 : "=r"(r[0]), "=r"(r[1]), "=r"(r[2]), "=r"(r[3]) : "r"(addr));
}

__device__ __forceinline__ void cp_async16(uint32_t smem, const void* g) {
    asm volatile("cp.async.cg.shared.global [%0], [%1], 16;" :: "r"(smem), "l"(g));
}

__device__ __forceinline__ float4 ldcg4(const uint32_t* p) {
    float4 v;
    asm volatile("ld.global.cg.v4.f32 {%0,%1,%2,%3}, [%4];"
                 : "=f"(v.x), "=f"(v.y), "=f"(v.z), "=f"(v.w) : "l"(p));
    return v;
}

__device__ __forceinline__ float rcp_(float x) {
    float r;
    asm("rcp.approx.f32 %0, %1;" : "=f"(r) : "f"(x));
    return r;
}
__device__ __forceinline__ float fast_sig(float x) { return rcp_(1.0f + __expf(-x)); }
__device__ __forceinline__ float fast_tanh(float x) { return 2.0f * rcp_(1.0f + __expf(-2.0f * x)) - 1.0f; }

__device__ __forceinline__ uint32_t pack_h2(float a, float b) {
    __half2 h = __floats2half2_rn(a, b);
    return *reinterpret_cast<uint32_t*>(&h);
}

// ---------------- prep: zero flags + h fragment buffers (every replay) ----------------
__global__ void prep_zero() {
    const int i = blockIdx.x * blockDim.x + threadIdx.x;
    if (i < NCTA_ALL * 32) g_flags[i] = 0u;
    const int n1 = 2 * 8192, n2 = 2 * 4096, n3 = 2 * 2048;
    uint32_t* p1 = (uint32_t*)g_b1;
    uint32_t* p2 = (uint32_t*)g_b2;
    uint32_t* p3 = (uint32_t*)g_b3;
    const int stride = gridDim.x * blockDim.x;
    for (int k = i; k < n1; k += stride) p1[k] = 0u;
    for (int k = i; k < n2; k += stride) p2[k] = 0u;
    for (int k = i; k < n3; k += stride) p3[k] = 0u;
}

// ---------------- fp32 -> bf16 conversion (vectorized) ----------------
__global__ void f2bf_kernel(const float* __restrict__ src, __nv_bfloat16* __restrict__ dst, int n4) {
    const int stride = gridDim.x * blockDim.x;
    __nv_bfloat162* d2 = (__nv_bfloat162*)dst;
    for (int i = blockIdx.x * blockDim.x + threadIdx.x; i < n4; i += stride) {
        const float4 v = ((const float4*)src)[i];
        d2[2 * i]     = __floats2bfloat162_rn(v.x, v.y);
        d2[2 * i + 1] = __floats2bfloat162_rn(v.z, v.w);
    }
}

// ---------------- bf16 GEMM (512 threads, 16 warps, 4-stage cp.async) ----------------
__global__ __launch_bounds__(512, 1) void gemm_bf16_bias(
    const __nv_bfloat16* __restrict__ A, const __nv_bfloat16* __restrict__ Bw,
    const float* __restrict__ b1, const float* __restrict__ b2,
    float* __restrict__ C, int M, int N, int K)
{
    constexpr int BM = 128, BN = 128, BK = 32;
    constexpr int LDA = BK + 8;
    constexpr int ST  = 4;
    extern __shared__ __nv_bfloat16 gsm[];
    __nv_bfloat16* As = gsm;
    __nv_bfloat16* Bs = gsm + ST * BM * LDA;

    const int tid  = threadIdx.x;
    const int lane = tid & 31;
    const int warp = tid >> 5;     // 0..15
    const int wm   = warp & 3;
    const int wn   = warp >> 2;    // 0..3

    const long bm = (long)blockIdx.y * BM;
    const long bn = (long)blockIdx.x * BN;

    const uint32_t aBase = (uint32_t)__cvta_generic_to_shared(As);
    const uint32_t bBase = (uint32_t)__cvta_generic_to_shared(Bs);

    const int cr = tid >> 2;          // 0..127
    const int cs = (tid & 3) * 8;

    auto issue = [&](int st, int k0) {
        cp_async16(aBase + (uint32_t)(st * BM * LDA + cr * LDA + cs) * 2,
                   A + (size_t)(bm + cr) * K + k0 + cs);
        cp_async16(bBase + (uint32_t)(st * BN * LDA + cr * LDA + cs) * 2,
                   Bw + (size_t)(bn + cr) * K + k0 + cs);
    };

    const int KT = K / BK;

    issue(0, 0);
    asm volatile("cp.async.commit_group;");
    issue(1, BK);
    asm volatile("cp.async.commit_group;");
    issue(2, 2 * BK);
    asm volatile("cp.async.commit_group;");

    float acc[2][4][4];
#pragma unroll
    for (int mf = 0; mf < 2; ++mf)
#pragma unroll
        for (int nt = 0; nt < 4; ++nt)
#pragma unroll
            for (int q = 0; q < 4; ++q) acc[mf][nt][q] = 0.0f;

    const int aRow  = wm * 32 + (lane & 15);
    const int aColH = (lane >> 4) << 3;
    const int bRow  = wn * 32 + (((lane >> 4) & 1) << 3) + (lane & 7);
    const int bColH = ((lane >> 3) & 1) << 3;

    for (int kt = 0; kt < KT; ++kt) {
        asm volatile("cp.async.wait_group 2;");
        __syncthreads();
        if (kt + 3 < KT) issue((kt + 3) & (ST - 1), (kt + 3) * BK);
        asm volatile("cp.async.commit_group;");

        const int st = kt & (ST - 1);
        const uint32_t aS = aBase + (uint32_t)(st * BM * LDA) * 2;
        const uint32_t bS = bBase + (uint32_t)(st * BN * LDA) * 2;

#pragma unroll
        for (int kf = 0; kf < 2; ++kf) {
            const int k0 = kf * 16;
            uint32_t afr[2][4];
#pragma unroll
            for (int mf = 0; mf < 2; ++mf)
                ldsm_x4(afr[mf], aS + (uint32_t)((aRow + mf * 16) * LDA + k0 + aColH) * 2);
            uint32_t bfr[2][4];
#pragma unroll
            for (int np = 0; np < 2; ++np)
                ldsm_x4(bfr[np], bS + (uint32_t)((bRow + np * 16) * LDA + k0 + bColH) * 2);
#pragma unroll
            for (int mf = 0; mf < 2; ++mf)
#pragma unroll
                for (int nt = 0; nt < 4; ++nt)
                    mma_bf16(acc[mf][nt], afr[mf], &bfr[nt >> 1][(nt & 1) * 2]);
        }
    }

#pragma unroll
    for (int mf = 0; mf < 2; ++mf) {
#pragma unroll
        for (int nt = 0; nt < 4; ++nt) {
            const long r0 = bm + wm * 32 + mf * 16 + (lane >> 2);
            const long c0 = bn + wn * 32 + nt * 8 + 2 * (lane & 3);
            const float bias0 = b1[c0] + b2[c0];
            const float bias1 = b1[c0 + 1] + b2[c0 + 1];
            C[r0 * N + c0]           = acc[mf][nt][0] + bias0;
            C[r0 * N + c0 + 1]       = acc[mf][nt][1] + bias1;
            C[(r0 + 8) * N + c0]     = acc[mf][nt][2] + bias0;
            C[(r0 + 8) * N + c0 + 1] = acc[mf][nt][3] + bias1;
        }
    }
}

// ---------------- fused 3-layer pipelined LSTM (fp16 mma, weights in registers) -------
// Generalized role: H hidden, KP proj input (0 => xg in gmem), HC units per CTA.
// 512 threads, 16 warps = 4(mi) x KSN(k-slices) x NTG(n-groups); B frags in registers.
// A fragments are loaded DIRECTLY from global ping-pong buffers with ld.global.cg
// (no cp.async staging -- LDGSTS issue throughput was the per-step bottleneck).
template <int H, int KP, int HC, int FIRST, bool LAST_ONLY>
__device__ __forceinline__ void lstm_role(
    char* dyn,
    const float* __restrict__ xg,
    const float* __restrict__ Wih,
    const float* __restrict__ Whh,
    const float* __restrict__ bih,
    const float* __restrict__ bhh,
    const uint32_t* __restrict__ bufP0, const uint32_t* __restrict__ bufP1,
    uint32_t* __restrict__ bufR0, uint32_t* __restrict__ bufR1,
    float* __restrict__ hlast,
    unsigned* __restrict__ flags,
    int ctaLocal, int myflag)
{
    constexpr int COLS = 4 * HC;
    constexpr int GSW  = COLS + 2;
    constexpr int NT   = COLS / 8;            // n-tiles of 8
    constexpr int NTG  = NT / 4;              // n-groups (warp covers 4 nt)
    constexpr int KSN  = 4 / NTG;             // k-slice count
    constexpr int KB_P = (KP > 0) ? KP / 16 : 0;
    constexpr int KBT  = KB_P + H / 16;       // total k16 blocks
    constexpr int KS   = KBT / KSN;           // kbs per warp
    constexpr int EPT  = HC / 8;              // elements per thread (1 or 2)
    constexpr int HSU  = 32 * HC;             // hS u32 count (CTA's fragment slice)
    static_assert(KS * KSN == KBT, "k split");
    static_assert(NTG * 4 == NT, "n split");

    float*    gS  = (float*)dyn;                             // KSN slabs * 64 * GSW
    uint32_t* hS  = (uint32_t*)(gS + KSN * 64 * GSW);        // HSU u32

    const int tid  = threadIdx.x;
    const int lane = tid & 31;
    const int w    = tid >> 5;
    const int grp  = lane >> 2;
    const int th4  = lane & 3;
    const int h0   = ctaLocal * HC;

    // ---- warp decomposition ----
    const int mi    = w & 3;
    const int wr    = w >> 2;               // 0..3
    const int ks    = wr & (KSN - 1);
    const int ntg_i = wr / KSN;

    // ---- build weight B fragments in registers (once) ----
    uint32_t bw[KS][4][2];
    {
        const int colb = lane >> 2;          // 0..7
        const int kk0  = (lane & 3) * 2;
#pragma unroll
        for (int q = 0; q < KS; ++q) {
            const int kbg = ks * KS + q;
#pragma unroll
            for (int nip = 0; nip < 4; ++nip) {
                const int c = (ntg_i * 4 + nip) * 8 + colb;   // 0..COLS-1
                const int g = c / HC, u = c % HC;
                const int row = g * H + h0 + u;
#pragma unroll
                for (int j = 0; j < 2; ++j) {
                    const int k = kbg * 16 + kk0 + j * 8;
                    float w0, w1;
                    if (KP > 0 && k < KP) {
                        const float* p = Wih + (size_t)row * KP + k;
                        w0 = p[0]; w1 = p[1];
                    } else {
                        const float* p = Whh + (size_t)row * H + (k - KP);
                        w0 = p[0]; w1 = p[1];
                    }
                    bw[q][nip][j] = pack_h2(w0, w1);
                }
            }
        }
    }

    // ---- elementwise ownership: thread -> (batch b, EPT units) ----
    const int b  = tid >> 3;                 // 0..63
    const int j0 = (tid & 7) * EPT;          // first unit index

    float cst[EPT];
    float xr[EPT][4];
    float bias[EPT][4];
#pragma unroll
    for (int e = 0; e < EPT; ++e) {
        cst[e] = 0.0f;
        const int kme = h0 + j0 + e;
        if (KP == 0) {
            const float* xp = xg + ((size_t)b * TT) * (4 * H) + kme;
#pragma unroll
            for (int g = 0; g < 4; ++g) xr[e][g] = xp[(size_t)g * H];
        } else {
#pragma unroll
            for (int g = 0; g < 4; ++g) {
                const int r = g * H + kme;
                bias[e][g] = bih[r] + bhh[r];
            }
        }
    }
    __syncthreads();

    for (int s = 0; s < TOTS; ++s) {
        const int t = s - FIRST;
        const bool active = (t >= 0) && (t < TT);

        // ---- mma: A fragments loaded directly from global (L2) ----
        if (active) {
            const uint32_t* srcP = (KP > 0) ? ((t & 1) ? bufP1 : bufP0) : (const uint32_t*)0;
            const uint32_t* srcR = (t & 1) ? bufR0 : bufR1;   // parity (t-1)&1

            // preload all A fragments (independent loads, deep MLP)
            float4 avv[KS];
#pragma unroll
            for (int q = 0; q < KS; ++q) {
                const int kb = ks * KS + q;
                const uint32_t* p = (KP > 0 && kb < KB_P)
                                        ? (srcP + ((size_t)(kb * 4 + mi) * 32 + lane) * 4)
                                        : (srcR + ((size_t)((kb - KB_P) * 4 + mi) * 32 + lane) * 4);
                avv[q] = ldcg4(p);
            }

            float acc[4][4];
#pragma unroll
            for (int nip = 0; nip < 4; ++nip)
#pragma unroll
                for (int q = 0; q < 4; ++q) acc[nip][q] = 0.0f;

#pragma unroll
            for (int q = 0; q < KS; ++q) {
                const uint32_t* au = (const uint32_t*)&avv[q];
#pragma unroll
                for (int nip = 0; nip < 4; ++nip)
                    mma_f16(acc[nip], au, bw[q][nip]);
            }

            float* gr = gS + ks * (64 * GSW) + (mi * 16 + grp) * GSW + 2 * th4;
#pragma unroll
            for (int nip = 0; nip < 4; ++nip) {
                const int cc = (ntg_i * 4 + nip) * 8;
                gr[cc]               = acc[nip][0];
                gr[cc + 1]           = acc[nip][1];
                gr[8 * GSW + cc]     = acc[nip][2];
                gr[8 * GSW + cc + 1] = acc[nip][3];
            }
        }
        __syncthreads();

        // ---- activations ----
        if (active) {
#pragma unroll
            for (int e = 0; e < EPT; ++e) {
                const int jj  = j0 + e;
                const int kme = h0 + jj;
                float pi, pf, pg, po;
                if (KP == 0) { pi = xr[e][0]; pf = xr[e][1]; pg = xr[e][2]; po = xr[e][3]; }
                else         { pi = bias[e][0]; pf = bias[e][1]; pg = bias[e][2]; po = bias[e][3]; }
#pragma unroll
                for (int sl = 0; sl < KSN; ++sl) {
                    const float* row = gS + sl * (64 * GSW) + b * GSW;
                    pi += row[jj];
                    pf += row[HC + jj];
                    pg += row[2 * HC + jj];
                    po += row[3 * HC + jj];
                }
                const float iv = fast_sig(pi), fv = fast_sig(pf);
                const float gv = fast_tanh(pg), ov = fast_sig(po);
                cst[e] = fv * cst[e] + iv * gv;
                const float h = ov * fast_tanh(cst[e]);

                // local fragment slice write (2B half)
                const int mib   = b >> 4;
                const int lanew = (b & 7) * 4 + ((jj & 7) >> 1);
                const int compl_ = (HC == 16)
                                       ? (((jj >> 3) & 1) * 2 + ((b >> 3) & 1))
                                       : ((b >> 3) & 1);
                const int compw = (HC == 16) ? 4 : 2;
                ((__half*)hS)[((mib * 32 + lanew) * compw + compl_) * 2 + (jj & 1)] = __float2half(h);

                if (LAST_ONLY && t == TT - 1)
                    hlast[(size_t)b * H + kme] = h;

                if (KP == 0 && t + 1 < TT) {
                    const float* xp = xg + ((size_t)b * TT + (t + 1)) * (4 * H) + kme;
#pragma unroll
                    for (int g = 0; g < 4; ++g) xr[e][g] = xp[(size_t)g * H];
                }
            }
        }
        __syncthreads();

        // ---- publish own h slice to global ping-pong buffer ----
        if (active) {
            uint32_t* gdst = (t & 1) ? bufR1 : bufR0;
            if (HC == 16) {
                if (tid < HSU / 4)
                    ((uint4*)(gdst + (size_t)ctaLocal * 512))[tid] = ((const uint4*)hS)[tid];
            } else {
                if (tid < HSU / 2) {
                    const int q = tid;       // (mi, lane) packed
                    uint32_t* dst = gdst + ((size_t)(ctaLocal >> 1) * 512)
                                    + ((size_t)((q >> 5) * 32 + (q & 31))) * 4
                                    + (ctaLocal & 1) * 2;
                    *(uint2*)dst = ((const uint2*)hS)[q];
                }
            }
        }
        __syncthreads();

        // ---- distributed flag barrier (all NCTA_ALL CTAs, every step) ----
        if (tid == 0) {
            asm volatile("st.release.gpu.global.u32 [%0], %1;"
                         :: "l"(flags + myflag * 32), "r"((unsigned)(s + 1)) : "memory");
        }
        if (tid < NCTA_ALL) {
            unsigned v;
            const unsigned tgt = (unsigned)(s + 1);
            unsigned* fp = flags + tid * 32;
            do {
                asm volatile("ld.acquire.gpu.global.u32 %0, [%1];" : "=r"(v) : "l"(fp) : "memory");
            } while (v < tgt);
        }
        __syncthreads();
    }
}

__global__ __launch_bounds__(512, 1) void lstm_fused(
    const float* __restrict__ xg1,
    const float* __restrict__ Whh1,
    const float* __restrict__ Wih2, const float* __restrict__ Whh2,
    const float* __restrict__ bih2, const float* __restrict__ bhh2,
    const float* __restrict__ Wih3, const float* __restrict__ Whh3,
    const float* __restrict__ bih3, const float* __restrict__ bhh3,
    float* __restrict__ h3out, unsigned* __restrict__ flags)
{
    extern __shared__ char dynls[];
    const int cb = blockIdx.x;
    if (cb < 16) {
        lstm_role<H1, 0, 16, 0, false>(dynls, xg1, nullptr, Whh1, nullptr, nullptr,
                                       nullptr, nullptr, g_b1[0], g_b1[1], nullptr,
                                       flags, cb, cb);
    } else if (cb < 32) {
        lstm_role<H2, H1, 8, 1, false>(dynls, nullptr, Wih2, Whh2, bih2, bhh2,
                                       g_b1[0], g_b1[1], g_b2[0], g_b2[1], nullptr,
                                       flags, cb - 16, cb);
    } else {
        lstm_role<H3, H2, 16, 2, true>(dynls, nullptr, Wih3, Whh3, bih3, bhh3,
                                       g_b2[0], g_b2[1], g_b3[0], g_b3[1], h3out,
                                       flags, cb - 32, cb);
    }
}

// ---------------- head: deep/wide/concat/output (256 threads) ----------------
__global__ __launch_bounds__(256) void head_kernel(
    const float* __restrict__ x,
    const float* __restrict__ h3last,
    const float* __restrict__ Wd, const float* __restrict__ bd,
    const float* __restrict__ Ww, const float* __restrict__ bw,
    const float* __restrict__ Wo, const float* __restrict__ bo,
    float* __restrict__ out)
{
    const int bidx = blockIdx.x;
    const int j = threadIdx.x & 31;
    const int s = threadIdx.x >> 5;
    __shared__ float red[8][33];

    const float* xrow = x + ((size_t)bidx * TT + (TT - 1)) * DD;
    const float* wwr = Ww + (size_t)j * DD;
    float acc = 0.0f;
    const int k0 = s * (DD / 8);
#pragma unroll 4
    for (int k = k0; k < k0 + DD / 8; k += 4) {
        const float4 xv = *(const float4*)&xrow[k];
        const float4 wv = *(const float4*)&wwr[k];
        acc = fmaf(xv.x, wv.x, acc);
        acc = fmaf(xv.y, wv.y, acc);
        acc = fmaf(xv.z, wv.z, acc);
        acc = fmaf(xv.w, wv.w, acc);
    }
    red[s][j] = acc;
    __syncthreads();

    if (s == 0) {
        float wide = bw[j];
#pragma unroll
        for (int q = 0; q < 8; ++q) wide += red[q][j];
        wide = fmaxf(wide, 0.0f);

        const float* hrow = h3last + (size_t)bidx * H3;
        const float* wdr = Wd + (size_t)j * H3;
        float deep = bd[j];
#pragma unroll
        for (int k = 0; k < H3; ++k) deep = fmaf(hrow[k], wdr[k], deep);
        deep = fmaxf(deep, 0.0f);

        float v = deep * Wo[j] + wide * Wo[32 + j];
#pragma unroll
        for (int off = 16; off > 0; off >>= 1)
            v += __shfl_xor_sync(0xffffffffu, v, off);
        if (j == 0) out[bidx] = v + bo[0];
    }
}

// ---------------- launch ----------------
extern "C" void kernel_launch(void* const* d_in, const int* in_sizes, int n_in,
                              void* d_out, int out_size) {
    const float* x    = (const float*)d_in[0];
    const float* Wih1 = (const float*)d_in[1];
    const float* Whh1 = (const float*)d_in[2];
    const float* bih1 = (const float*)d_in[3];
    const float* bhh1 = (const float*)d_in[4];
    const float* Wih2 = (const float*)d_in[5];
    const float* Whh2 = (const float*)d_in[6];
    const float* bih2 = (const float*)d_in[7];
    const float* bhh2 = (const float*)d_in[8];
    const float* Wih3 = (const float*)d_in[9];
    const float* Whh3 = (const float*)d_in[10];
    const float* bih3 = (const float*)d_in[11];
    const float* bhh3 = (const float*)d_in[12];
    const float* Wd   = (const float*)d_in[13];
    const float* bd   = (const float*)d_in[14];
    const float* Ww   = (const float*)d_in[15];
    const float* bw   = (const float*)d_in[16];
    const float* Wo   = (const float*)d_in[17];
    const float* bo   = (const float*)d_in[18];
    float* out = (float*)d_out;

    float *xg1, *h3;
    __nv_bfloat16 *xbf, *W1bf;
    unsigned* flags;
    cudaGetSymbolAddress((void**)&xg1,   g_xg1);
    cudaGetSymbolAddress((void**)&h3,    g_h3);
    cudaGetSymbolAddress((void**)&xbf,   g_xbf);
    cudaGetSymbolAddress((void**)&W1bf,  g_W1bf);
    cudaGetSymbolAddress((void**)&flags, g_flags);

    const int M = BB * TT;  // 32768

    prep_zero<<<60, 512>>>();

    // convert x and Wih1 to bf16 for the big GEMM
    f2bf_kernel<<<4096, 256>>>(x,    xbf,  (BB * TT * DD) / 4);
    f2bf_kernel<<<512,  256>>>(Wih1, W1bf, (4 * H1 * DD) / 4);

    // layer-1 input projection: xg1 = x @ Wih1^T + bih1 + bhh1
    {
        const int gsmem = 4 * (128 + 128) * 40 * 2;  // 81920 B
        cudaFuncSetAttribute(gemm_bf16_bias, cudaFuncAttributeMaxDynamicSharedMemorySize, gsmem);
        dim3 grid((4 * H1) / 128, M / 128);
        gemm_bf16_bias<<<grid, 512, gsmem>>>(xbf, W1bf, bih1, bhh1, xg1, M, 4 * H1, DD);
    }

    // fused pipelined 3-layer recurrence (36 CTAs, distributed flag barrier)
    {
        // max over roles: L2 = 4*64*34*4 + 1KB ~= 36KB
        const int dynBytes = 40960;
        cudaFuncSetAttribute(lstm_fused, cudaFuncAttributeMaxDynamicSharedMemorySize, dynBytes);
        lstm_fused<<<NCTA_ALL, 512, dynBytes>>>(xg1, Whh1,
                                                Wih2, Whh2, bih2, bhh2,
                                                Wih3, Whh3, bih3, bhh3,
                                                h3, flags);
    }

    // head
    head_kernel<<<BB, 256>>>(x, h3, Wd, bd, Ww, bw, Wo, bo, out);

    (void)in_sizes; (void)n_in; (void)out_size;
}

// round 10
// speedup vs baseline: 1.7112x; 1.1167x over previous
#include <cuda_runtime.h>
#include <cuda_bf16.h>
#include <cuda_fp16.h>
#include <cstdint>
#include <math.h>

// Problem dims (fixed by the reference)
#define BB 64
#define TT 512
#define DD 2048
#define H1 256
#define H2 128
#define H3 64

#define NCTA_ALL 36      // 16 (L1) + 16 (L2) + 4 (L3)
#define TOTS (TT + 2)
#define RING 4

// ---------------- scratch (static device buffers; no allocation) ----------------
__device__ __align__(16) float g_xg1[(size_t)BB * TT * 4 * H1];   // 32768 x 1024
__device__ __align__(16) __nv_bfloat16 g_xbf[(size_t)BB * TT * DD];
__device__ __align__(16) __nv_bfloat16 g_W1bf[4 * H1 * DD];
__device__ __align__(16) float g_h3[BB * H3];         // layer-3 last h (fp32)
// h ring buffers (fp16 mma A-fragment layout, u32 units), 4 deep
__device__ __align__(16) uint32_t g_b1[RING][8192];   // h1: 16 kb x 512 u32
__device__ __align__(16) uint32_t g_b2[RING][4096];   // h2:  8 kb x 512
__device__ __align__(16) uint32_t g_b3[RING][2048];   // h3:  4 kb x 512
__device__ unsigned g_flags[NCTA_ALL * 32];           // one flag per CTA, 128B apart

// ---------------- helpers ----------------
__device__ __forceinline__ void mma_bf16(float* c, const uint32_t* a, const uint32_t* b) {
    asm volatile(
        "mma.sync.aligned.m16n8k16.row.col.f32.bf16.bf16.f32 "
        "{%0,%1,%2,%3}, {%4,%5,%6,%7}, {%8,%9}, {%0,%1,%2,%3};"
        : "+f"(c[0]), "+f"(c[1]), "+f"(c[2]), "+f"(c[3])
        : "r"(a[0]), "r"(a[1]), "r"(a[2]), "r"(a[3]), "r"(b[0]), "r"(b[1]));
}

__device__ __forceinline__ void mma_f16(float* c, const uint32_t* a, const uint32_t* b) {
    asm volatile(
        "mma.sync.aligned.m16n8k16.row.col.f32.f16.f16.f32 "
        "{%0,%1,%2,%3}, {%4,%5,%6,%7}, {%8,%9}, {%0,%1,%2,%3};"
        : "+f"(c[0]), "+f"(c[1]), "+f"(c[2]), "+f"(c[3])
        : "r"(a[0]), "r"(a[1]), "r"(a[2]), "r"(a[3]), "r"(b[0]), "r"(b[1]));
}

__device__ __forceinline__ void ldsm_x4(uint32_t* r, uint32_t addr) {
    asm volatile("ldmatrix.sync.aligned.m8n8.x4.shared.b16 {%0,%1,%2,%3}, [%4];"
                 : "=r"(r[0]), "=r"(r[1]), "=r"(r[2]), "=r"(r[3]) : "r"(addr));
}

__device__ __forceinline__ void cp_async16(uint32_t smem, const void* g) {
    asm volatile("cp.async.cg.shared.global [%0], [%1], 16;" :: "r"(smem), "l"(g));
}

__device__ __forceinline__ float4 ldcg4(const uint32_t* p) {
    float4 v;
    asm volatile("ld.global.cg.v4.f32 {%0,%1,%2,%3}, [%4];"
                 : "=f"(v.x), "=f"(v.y), "=f"(v.z), "=f"(v.w) : "l"(p));
    return v;
}

__device__ __forceinline__ float rcp_(float x) {
    float r;
    asm("rcp.approx.f32 %0, %1;" : "=f"(r) : "f"(x));
    return r;
}
__device__ __forceinline__ float fast_sig(float x) { return rcp_(1.0f + __expf(-x)); }
__device__ __forceinline__ float fast_tanh(float x) { return 2.0f * rcp_(1.0f + __expf(-2.0f * x)) - 1.0f; }

__device__ __forceinline__ uint32_t pack_h2(float a, float b) {
    __half2 h = __floats2half2_rn(a, b);
    return *reinterpret_cast<uint32_t*>(&h);
}

// ---------------- prep: zero flags + h ring buffers (every replay) ----------------
__global__ void prep_zero() {
    const int i = blockIdx.x * blockDim.x + threadIdx.x;
    if (i < NCTA_ALL * 32) g_flags[i] = 0u;
    const int n1 = RING * 8192, n2 = RING * 4096, n3 = RING * 2048;
    uint32_t* p1 = (uint32_t*)g_b1;
    uint32_t* p2 = (uint32_t*)g_b2;
    uint32_t* p3 = (uint32_t*)g_b3;
    const int stride = gridDim.x * blockDim.x;
    for (int k = i; k < n1; k += stride) p1[k] = 0u;
    for (int k = i; k < n2; k += stride) p2[k] = 0u;
    for (int k = i; k < n3; k += stride) p3[k] = 0u;
}

// ---------------- fp32 -> bf16 conversion (vectorized) ----------------
__global__ void f2bf_kernel(const float* __restrict__ src, __nv_bfloat16* __restrict__ dst, int n4) {
    const int stride = gridDim.x * blockDim.x;
    __nv_bfloat162* d2 = (__nv_bfloat162*)dst;
    for (int i = blockIdx.x * blockDim.x + threadIdx.x; i < n4; i += stride) {
        const float4 v = ((const float4*)src)[i];
        d2[2 * i]     = __floats2bfloat162_rn(v.x, v.y);
        d2[2 * i + 1] = __floats2bfloat162_rn(v.z, v.w);
    }
}

// ---------------- bf16 GEMM (512 threads, 16 warps, 4-stage cp.async) ----------------
__global__ __launch_bounds__(512, 1) void gemm_bf16_bias(
    const __nv_bfloat16* __restrict__ A, const __nv_bfloat16* __restrict__ Bw,
    const float* __restrict__ b1, const float* __restrict__ b2,
    float* __restrict__ C, int M, int N, int K)
{
    constexpr int BM = 128, BN = 128, BK = 32;
    constexpr int LDA = BK + 8;
    constexpr int ST  = 4;
    extern __shared__ __nv_bfloat16 gsm[];
    __nv_bfloat16* As = gsm;
    __nv_bfloat16* Bs = gsm + ST * BM * LDA;

    const int tid  = threadIdx.x;
    const int lane = tid & 31;
    const int warp = tid >> 5;     // 0..15
    const int wm   = warp & 3;
    const int wn   = warp >> 2;    // 0..3

    const long bm = (long)blockIdx.y * BM;
    const long bn = (long)blockIdx.x * BN;

    const uint32_t aBase = (uint32_t)__cvta_generic_to_shared(As);
    const uint32_t bBase = (uint32_t)__cvta_generic_to_shared(Bs);

    const int cr = tid >> 2;          // 0..127
    const int cs = (tid & 3) * 8;

    auto issue = [&](int st, int k0) {
        cp_async16(aBase + (uint32_t)(st * BM * LDA + cr * LDA + cs) * 2,
                   A + (size_t)(bm + cr) * K + k0 + cs);
        cp_async16(bBase + (uint32_t)(st * BN * LDA + cr * LDA + cs) * 2,
                   Bw + (size_t)(bn + cr) * K + k0 + cs);
    };

    const int KT = K / BK;

    issue(0, 0);
    asm volatile("cp.async.commit_group;");
    issue(1, BK);
    asm volatile("cp.async.commit_group;");
    issue(2, 2 * BK);
    asm volatile("cp.async.commit_group;");

    float acc[2][4][4];
#pragma unroll
    for (int mf = 0; mf < 2; ++mf)
#pragma unroll
        for (int nt = 0; nt < 4; ++nt)
#pragma unroll
            for (int q = 0; q < 4; ++q) acc[mf][nt][q] = 0.0f;

    const int aRow  = wm * 32 + (lane & 15);
    const int aColH = (lane >> 4) << 3;
    const int bRow  = wn * 32 + (((lane >> 4) & 1) << 3) + (lane & 7);
    const int bColH = ((lane >> 3) & 1) << 3;

    for (int kt = 0; kt < KT; ++kt) {
        asm volatile("cp.async.wait_group 2;");
        __syncthreads();
        if (kt + 3 < KT) issue((kt + 3) & (ST - 1), (kt + 3) * BK);
        asm volatile("cp.async.commit_group;");

        const int st = kt & (ST - 1);
        const uint32_t aS = aBase + (uint32_t)(st * BM * LDA) * 2;
        const uint32_t bS = bBase + (uint32_t)(st * BN * LDA) * 2;

#pragma unroll
        for (int kf = 0; kf < 2; ++kf) {
            const int k0 = kf * 16;
            uint32_t afr[2][4];
#pragma unroll
            for (int mf = 0; mf < 2; ++mf)
                ldsm_x4(afr[mf], aS + (uint32_t)((aRow + mf * 16) * LDA + k0 + aColH) * 2);
            uint32_t bfr[2][4];
#pragma unroll
            for (int np = 0; np < 2; ++np)
                ldsm_x4(bfr[np], bS + (uint32_t)((bRow + np * 16) * LDA + k0 + bColH) * 2);
#pragma unroll
            for (int mf = 0; mf < 2; ++mf)
#pragma unroll
                for (int nt = 0; nt < 4; ++nt)
                    mma_bf16(acc[mf][nt], afr[mf], &bfr[nt >> 1][(nt & 1) * 2]);
        }
    }

#pragma unroll
    for (int mf = 0; mf < 2; ++mf) {
#pragma unroll
        for (int nt = 0; nt < 4; ++nt) {
            const long r0 = bm + wm * 32 + mf * 16 + (lane >> 2);
            const long c0 = bn + wn * 32 + nt * 8 + 2 * (lane & 3);
            const float bias0 = b1[c0] + b2[c0];
            const float bias1 = b1[c0 + 1] + b2[c0 + 1];
            C[r0 * N + c0]           = acc[mf][nt][0] + bias0;
            C[r0 * N + c0 + 1]       = acc[mf][nt][1] + bias1;
            C[(r0 + 8) * N + c0]     = acc[mf][nt][2] + bias0;
            C[(r0 + 8) * N + c0 + 1] = acc[mf][nt][3] + bias1;
        }
    }
}

// ---------------- fused 3-layer pipelined LSTM, dependency-graph sync ----------------
// ROLE: 1/2/3. H hidden, KP proj input (0 => xg in gmem), HC units per CTA.
// h exchanged via 4-deep ring buffers in fp16 A-fragment layout; per-CTA release
// flags carry the completed global step; each CTA waits only on its producers.
template <int ROLE, int H, int KP, int HC, int FIRST, bool LAST_ONLY>
__device__ __forceinline__ void lstm_role(
    char* dyn,
    const float* __restrict__ xg,
    const float* __restrict__ Wih,
    const float* __restrict__ Whh,
    const float* __restrict__ bih,
    const float* __restrict__ bhh,
    const uint32_t* __restrict__ ringP, int strideP,
    uint32_t* __restrict__ ringR, int strideR,
    float* __restrict__ hlast,
    unsigned* __restrict__ flags,
    int ctaLocal, int myflag)
{
    constexpr int COLS = 4 * HC;
    constexpr int GSW  = COLS + 2;
    constexpr int NT   = COLS / 8;            // n-tiles of 8
    constexpr int NTG  = NT / 4;              // n-groups (warp covers 4 nt)
    constexpr int KSN  = 4 / NTG;             // k-slice count
    constexpr int KB_P = (KP > 0) ? KP / 16 : 0;
    constexpr int KBT  = KB_P + H / 16;       // total k16 blocks
    constexpr int KS   = KBT / KSN;           // kbs per warp
    constexpr int EPT  = HC / 8;              // elements per thread (1 or 2)
    static_assert(KS * KSN == KBT, "k split");
    static_assert(NTG * 4 == NT, "n split");

    float* gS = (float*)dyn;                  // KSN slabs * 64 * GSW

    const int tid  = threadIdx.x;
    const int lane = tid & 31;
    const int w    = tid >> 5;
    const int grp  = lane >> 2;
    const int th4  = lane & 3;
    const int h0   = ctaLocal * HC;

    // ---- warp decomposition ----
    const int mi    = w & 3;
    const int wr    = w >> 2;               // 0..3
    const int ks    = wr & (KSN - 1);
    const int ntg_i = wr / KSN;

    // ---- build weight B fragments in registers (once) ----
    uint32_t bw[KS][4][2];
    {
        const int colb = lane >> 2;          // 0..7
        const int kk0  = (lane & 3) * 2;
#pragma unroll
        for (int q = 0; q < KS; ++q) {
            const int kbg = ks * KS + q;
#pragma unroll
            for (int nip = 0; nip < 4; ++nip) {
                const int c = (ntg_i * 4 + nip) * 8 + colb;   // 0..COLS-1
                const int g = c / HC, u = c % HC;
                const int row = g * H + h0 + u;
#pragma unroll
                for (int j = 0; j < 2; ++j) {
                    const int k = kbg * 16 + kk0 + j * 8;
                    float w0, w1;
                    if (KP > 0 && k < KP) {
                        const float* p = Wih + (size_t)row * KP + k;
                        w0 = p[0]; w1 = p[1];
                    } else {
                        const float* p = Whh + (size_t)row * H + (k - KP);
                        w0 = p[0]; w1 = p[1];
                    }
                    bw[q][nip][j] = pack_h2(w0, w1);
                }
            }
        }
    }

    // ---- elementwise ownership: thread -> (batch b, EPT units) ----
    const int b  = tid >> 3;                 // 0..63
    const int j0 = (tid & 7) * EPT;          // first unit index

    float cst[EPT];
    float xr[EPT][4];
    float bias[EPT][4];
#pragma unroll
    for (int e = 0; e < EPT; ++e) {
        cst[e] = 0.0f;
        const int kme = h0 + j0 + e;
        if (KP == 0) {
            const float* xp = xg + ((size_t)b * TT) * (4 * H) + kme;
#pragma unroll
            for (int g = 0; g < 4; ++g) xr[e][g] = xp[(size_t)g * H];
        } else {
#pragma unroll
            for (int g = 0; g < 4; ++g) {
                const int r = g * H + kme;
                bias[e][g] = bih[r] + bhh[r];
            }
        }
    }

    // ---- output fragment index (A-fragment layout of my h values) ----
    const int mib   = b >> 4;
    const int lanew = (b & 7) * 4 + ((j0 & 7) >> 1);   // j0 even when EPT=2
    // HC==16: one full u32 per thread; HC==8: one half per thread
    const int out_u32 = (HC == 16)
        ? (ctaLocal * 512 + (mib * 32 + lanew) * 4 + ((j0 >> 3) & 1) * 2 + ((b >> 3) & 1))
        : ((ctaLocal >> 1) * 512 + (mib * 32 + lanew) * 4 + (ctaLocal & 1) * 2 + ((b >> 3) & 1));

    __syncthreads();

    for (int s = 0; s < TOTS; ++s) {
        const int t = s - FIRST;
        const bool active = (t >= 0) && (t < TT);

        // ---- dependency wait (layer-local thresholds) ----
        {
            int thr;
            if (ROLE == 1)      thr = (tid < 16) ? s : ((tid < 32) ? s - 2 : -1000000);
            else if (ROLE == 2) thr = (tid < 32) ? s : s - 2;
            else                thr = (tid < 16) ? -1000000 : s;
            if (tid < NCTA_ALL && thr > 0) {
                const unsigned utg = (unsigned)thr;
                unsigned v;
                unsigned* fp = flags + tid * 32;
                do {
                    asm volatile("ld.acquire.gpu.global.u32 %0, [%1];" : "=r"(v) : "l"(fp) : "memory");
                } while (v < utg);
            }
        }
        __syncthreads();

        // ---- mma: A fragments loaded directly from ring buffers (L2) ----
        if (active) {
            const uint32_t* srcP = (KP > 0) ? (ringP + (size_t)(t & (RING - 1)) * strideP)
                                            : (const uint32_t*)0;
            const uint32_t* srcR = ringR + (size_t)((t - 1) & (RING - 1)) * strideR;

            float4 avv[KS];
#pragma unroll
            for (int q = 0; q < KS; ++q) {
                const int kb = ks * KS + q;
                const uint32_t* p = (KP > 0 && kb < KB_P)
                                        ? (srcP + ((size_t)(kb * 4 + mi) * 32 + lane) * 4)
                                        : (srcR + ((size_t)((kb - KB_P) * 4 + mi) * 32 + lane) * 4);
                avv[q] = ldcg4(p);
            }

            float acc[4][4];
#pragma unroll
            for (int nip = 0; nip < 4; ++nip)
#pragma unroll
                for (int q = 0; q < 4; ++q) acc[nip][q] = 0.0f;

#pragma unroll
            for (int q = 0; q < KS; ++q) {
                const uint32_t* au = (const uint32_t*)&avv[q];
#pragma unroll
                for (int nip = 0; nip < 4; ++nip)
                    mma_f16(acc[nip], au, bw[q][nip]);
            }

            float* gr = gS + ks * (64 * GSW) + (mi * 16 + grp) * GSW + 2 * th4;
#pragma unroll
            for (int nip = 0; nip < 4; ++nip) {
                const int cc = (ntg_i * 4 + nip) * 8;
                gr[cc]               = acc[nip][0];
                gr[cc + 1]           = acc[nip][1];
                gr[8 * GSW + cc]     = acc[nip][2];
                gr[8 * GSW + cc + 1] = acc[nip][3];
            }
        }
        __syncthreads();

        // ---- activations + direct STG of h into ring (A-fragment layout) ----
        if (active) {
            uint32_t* dstR = ringR + (size_t)(t & (RING - 1)) * strideR;
            float hv[EPT];
#pragma unroll
            for (int e = 0; e < EPT; ++e) {
                const int jj  = j0 + e;
                float pi, pf, pg, po;
                if (KP == 0) { pi = xr[e][0]; pf = xr[e][1]; pg = xr[e][2]; po = xr[e][3]; }
                else         { pi = bias[e][0]; pf = bias[e][1]; pg = bias[e][2]; po = bias[e][3]; }
#pragma unroll
                for (int sl = 0; sl < KSN; ++sl) {
                    const float* row = gS + sl * (64 * GSW) + b * GSW;
                    pi += row[jj];
                    pf += row[HC + jj];
                    pg += row[2 * HC + jj];
                    po += row[3 * HC + jj];
                }
                const float iv = fast_sig(pi), fv = fast_sig(pf);
                const float gv = fast_tanh(pg), ov = fast_sig(po);
                cst[e] = fv * cst[e] + iv * gv;
                hv[e] = ov * fast_tanh(cst[e]);

                if (LAST_ONLY && t == TT - 1)
                    hlast[(size_t)b * H + h0 + jj] = hv[e];

                if (KP == 0 && t + 1 < TT) {
                    const float* xp = xg + ((size_t)b * TT + (t + 1)) * (4 * H) + h0 + jj;
#pragma unroll
                    for (int g = 0; g < 4; ++g) xr[e][g] = xp[(size_t)g * H];
                }
            }
            if (HC == 16) {
                dstR[out_u32] = pack_h2(hv[0], hv[1]);
            } else {
                ((__half*)dstR)[out_u32 * 2 + (j0 & 1)] = __float2half(hv[0]);
            }
        }
        __syncthreads();   // order STGs into CTA causality before the release

        // ---- release my flag (completed global step s) ----
        if (tid == 0) {
            asm volatile("st.release.gpu.global.u32 [%0], %1;"
                         :: "l"(flags + myflag * 32), "r"((unsigned)(s + 1)) : "memory");
        }
    }
}

__global__ __launch_bounds__(512, 1) void lstm_fused(
    const float* __restrict__ xg1,
    const float* __restrict__ Whh1,
    const float* __restrict__ Wih2, const float* __restrict__ Whh2,
    const float* __restrict__ bih2, const float* __restrict__ bhh2,
    const float* __restrict__ Wih3, const float* __restrict__ Whh3,
    const float* __restrict__ bih3, const float* __restrict__ bhh3,
    float* __restrict__ h3out, unsigned* __restrict__ flags)
{
    extern __shared__ char dynls[];
    const int cb = blockIdx.x;
    if (cb < 16) {
        lstm_role<1, H1, 0, 16, 0, false>(dynls, xg1, nullptr, Whh1, nullptr, nullptr,
                                          nullptr, 0, (uint32_t*)g_b1, 8192, nullptr,
                                          flags, cb, cb);
    } else if (cb < 32) {
        lstm_role<2, H2, H1, 8, 1, false>(dynls, nullptr, Wih2, Whh2, bih2, bhh2,
                                          (const uint32_t*)g_b1, 8192, (uint32_t*)g_b2, 4096,
                                          nullptr, flags, cb - 16, cb);
    } else {
        lstm_role<3, H3, H2, 16, 2, true>(dynls, nullptr, Wih3, Whh3, bih3, bhh3,
                                          (const uint32_t*)g_b2, 4096, (uint32_t*)g_b3, 2048,
                                          h3out, flags, cb - 32, cb);
    }
}

// ---------------- head: deep/wide/concat/output (256 threads) ----------------
__global__ __launch_bounds__(256) void head_kernel(
    const float* __restrict__ x,
    const float* __restrict__ h3last,
    const float* __restrict__ Wd, const float* __restrict__ bd,
    const float* __restrict__ Ww, const float* __restrict__ bw,
    const float* __restrict__ Wo, const float* __restrict__ bo,
    float* __restrict__ out)
{
    const int bidx = blockIdx.x;
    const int j = threadIdx.x & 31;
    const int s = threadIdx.x >> 5;
    __shared__ float red[8][33];

    const float* xrow = x + ((size_t)bidx * TT + (TT - 1)) * DD;
    const float* wwr = Ww + (size_t)j * DD;
    float acc = 0.0f;
    const int k0 = s * (DD / 8);
#pragma unroll 4
    for (int k = k0; k < k0 + DD / 8; k += 4) {
        const float4 xv = *(const float4*)&xrow[k];
        const float4 wv = *(const float4*)&wwr[k];
        acc = fmaf(xv.x, wv.x, acc);
        acc = fmaf(xv.y, wv.y, acc);
        acc = fmaf(xv.z, wv.z, acc);
        acc = fmaf(xv.w, wv.w, acc);
    }
    red[s][j] = acc;
    __syncthreads();

    if (s == 0) {
        float wide = bw[j];
#pragma unroll
        for (int q = 0; q < 8; ++q) wide += red[q][j];
        wide = fmaxf(wide, 0.0f);

        const float* hrow = h3last + (size_t)bidx * H3;
        const float* wdr = Wd + (size_t)j * H3;
        float deep = bd[j];
#pragma unroll
        for (int k = 0; k < H3; ++k) deep = fmaf(hrow[k], wdr[k], deep);
        deep = fmaxf(deep, 0.0f);

        float v = deep * Wo[j] + wide * Wo[32 + j];
#pragma unroll
        for (int off = 16; off > 0; off >>= 1)
            v += __shfl_xor_sync(0xffffffffu, v, off);
        if (j == 0) out[bidx] = v + bo[0];
    }
}

// ---------------- launch ----------------
extern "C" void kernel_launch(void* const* d_in, const int* in_sizes, int n_in,
                              void* d_out, int out_size) {
    const float* x    = (const float*)d_in[0];
    const float* Wih1 = (const float*)d_in[1];
    const float* Whh1 = (const float*)d_in[2];
    const float* bih1 = (const float*)d_in[3];
    const float* bhh1 = (const float*)d_in[4];
    const float* Wih2 = (const float*)d_in[5];
    const float* Whh2 = (const float*)d_in[6];
    const float* bih2 = (const float*)d_in[7];
    const float* bhh2 = (const float*)d_in[8];
    const float* Wih3 = (const float*)d_in[9];
    const float* Whh3 = (const float*)d_in[10];
    const float* bih3 = (const float*)d_in[11];
    const float* bhh3 = (const float*)d_in[12];
    const float* Wd   = (const float*)d_in[13];
    const float* bd   = (const float*)d_in[14];
    const float* Ww   = (const float*)d_in[15];
    const float* bw   = (const float*)d_in[16];
    const float* Wo   = (const float*)d_in[17];
    const float* bo   = (const float*)d_in[18];
    float* out = (float*)d_out;

    float *xg1, *h3;
    __nv_bfloat16 *xbf, *W1bf;
    unsigned* flags;
    cudaGetSymbolAddress((void**)&xg1,   g_xg1);
    cudaGetSymbolAddress((void**)&h3,    g_h3);
    cudaGetSymbolAddress((void**)&xbf,   g_xbf);
    cudaGetSymbolAddress((void**)&W1bf,  g_W1bf);
    cudaGetSymbolAddress((void**)&flags, g_flags);

    const int M = BB * TT;  // 32768

    prep_zero<<<60, 512>>>();

    // convert x and Wih1 to bf16 for the big GEMM
    f2bf_kernel<<<4096, 256>>>(x,    xbf,  (BB * TT * DD) / 4);
    f2bf_kernel<<<512,  256>>>(Wih1, W1bf, (4 * H1 * DD) / 4);

    // layer-1 input projection: xg1 = x @ Wih1^T + bih1 + bhh1
    {
        const int gsmem = 4 * (128 + 128) * 40 * 2;  // 81920 B
        cudaFuncSetAttribute(gemm_bf16_bias, cudaFuncAttributeMaxDynamicSharedMemorySize, gsmem);
        dim3 grid((4 * H1) / 128, M / 128);
        gemm_bf16_bias<<<grid, 512, gsmem>>>(xbf, W1bf, bih1, bhh1, xg1, M, 4 * H1, DD);
    }

    // fused pipelined 3-layer recurrence (36 CTAs, dependency-graph sync)
    {
        // max over roles: L2 = 4*64*34*4 = 34816 B
        const int dynBytes = 36864;
        cudaFuncSetAttribute(lstm_fused, cudaFuncAttributeMaxDynamicSharedMemorySize, dynBytes);
        lstm_fused<<<NCTA_ALL, 512, dynBytes>>>(xg1, Whh1,
                                                Wih2, Whh2, bih2, bhh2,
                                                Wih3, Whh3, bih3, bhh3,
                                                h3, flags);
    }

    // head
    head_kernel<<<BB, 256>>>(x, h3, Wd, bd, Ww, bw, Wo, bo, out);

    (void)in_sizes; (void)n_in; (void)out_size;
}

// round 11
// speedup vs baseline: 1.7364x; 1.0147x over previous
#include <cuda_runtime.h>
#include <cuda_bf16.h>
#include <cuda_fp16.h>
#include <cstdint>
#include <math.h>

// Problem dims (fixed by the reference)
#define BB 64
#define TT 512
#define DD 2048
#define H1 256
#define H2 128
#define H3 64

#define NCTA_ALL 36      // 16 (L1) + 16 (L2) + 4 (L3)
#define TOTS (TT + 2)
#define RING 8

// ---------------- scratch (static device buffers; no allocation) ----------------
__device__ __align__(16) float g_xg1[(size_t)BB * TT * 4 * H1];   // 32768 x 1024
__device__ __align__(16) __nv_bfloat16 g_xbf[(size_t)BB * TT * DD];
__device__ __align__(16) __nv_bfloat16 g_W1bf[4 * H1 * DD];
__device__ __align__(16) float g_h3[BB * H3];         // layer-3 last h (fp32)
// h ring buffers (fp16 mma A-fragment layout, u32 units), 8 deep
__device__ __align__(16) uint32_t g_b1[RING][8192];   // h1: 16 kb x 512 u32
__device__ __align__(16) uint32_t g_b2[RING][4096];   // h2:  8 kb x 512
__device__ __align__(16) uint32_t g_b3[RING][2048];   // h3:  4 kb x 512
__device__ unsigned g_flags[NCTA_ALL * 32];           // one flag per CTA, 128B apart

// ---------------- helpers ----------------
__device__ __forceinline__ void mma_bf16(float* c, const uint32_t* a, const uint32_t* b) {
    asm volatile(
        "mma.sync.aligned.m16n8k16.row.col.f32.bf16.bf16.f32 "
        "{%0,%1,%2,%3}, {%4,%5,%6,%7}, {%8,%9}, {%0,%1,%2,%3};"
        : "+f"(c[0]), "+f"(c[1]), "+f"(c[2]), "+f"(c[3])
        : "r"(a[0]), "r"(a[1]), "r"(a[2]), "r"(a[3]), "r"(b[0]), "r"(b[1]));
}

__device__ __forceinline__ void mma_f16(float* c, const uint32_t* a, const uint32_t* b) {
    asm volatile(
        "mma.sync.aligned.m16n8k16.row.col.f32.f16.f16.f32 "
        "{%0,%1,%2,%3}, {%4,%5,%6,%7}, {%8,%9}, {%0,%1,%2,%3};"
        : "+f"(c[0]), "+f"(c[1]), "+f"(c[2]), "+f"(c[3])
        : "r"(a[0]), "r"(a[1]), "r"(a[2]), "r"(a[3]), "r"(b[0]), "r"(b[1]));
}

__device__ __forceinline__ void ldsm_x4(uint32_t* r, uint32_t addr) {
    asm volatile("ldmatrix.sync.aligned.m8n8.x4.shared.b16 {%0,%1,%2,%3}, [%4];"
                 : "=r"(r[0]), "=r"(r[1]), "=r"(r[2]), "=r"(r[3]) : "r"(addr));
}

__device__ __forceinline__ void cp_async16(uint32_t smem, const void* g) {
    asm volatile("cp.async.cg.shared.global [%0], [%1], 16;" :: "r"(smem), "l"(g));
}

__device__ __forceinline__ float4 ldcg4(const uint32_t* p) {
    float4 v;
    asm volatile("ld.global.cg.v4.f32 {%0,%1,%2,%3}, [%4];"
                 : "=f"(v.x), "=f"(v.y), "=f"(v.z), "=f"(v.w) : "l"(p));
    return v;
}

__device__ __forceinline__ float rcp_(float x) {
    float r;
    asm("rcp.approx.f32 %0, %1;" : "=f"(r) : "f"(x));
    return r;
}
__device__ __forceinline__ float fast_sig(float x) { return rcp_(1.0f + __expf(-x)); }
__device__ __forceinline__ float fast_tanh(float x) { return 2.0f * rcp_(1.0f + __expf(-2.0f * x)) - 1.0f; }

__device__ __forceinline__ uint32_t pack_h2(float a, float b) {
    __half2 h = __floats2half2_rn(a, b);
    return *reinterpret_cast<uint32_t*>(&h);
}

// ---------------- prep: zero flags + h ring buffers (every replay) ----------------
__global__ void prep_zero() {
    const int i = blockIdx.x * blockDim.x + threadIdx.x;
    if (i < NCTA_ALL * 32) g_flags[i] = 0u;
    const int n1 = RING * 8192, n2 = RING * 4096, n3 = RING * 2048;
    uint32_t* p1 = (uint32_t*)g_b1;
    uint32_t* p2 = (uint32_t*)g_b2;
    uint32_t* p3 = (uint32_t*)g_b3;
    const int stride = gridDim.x * blockDim.x;
    for (int k = i; k < n1; k += stride) p1[k] = 0u;
    for (int k = i; k < n2; k += stride) p2[k] = 0u;
    for (int k = i; k < n3; k += stride) p3[k] = 0u;
}

// ---------------- fp32 -> bf16 conversion (vectorized) ----------------
__global__ void f2bf_kernel(const float* __restrict__ src, __nv_bfloat16* __restrict__ dst, int n4) {
    const int stride = gridDim.x * blockDim.x;
    __nv_bfloat162* d2 = (__nv_bfloat162*)dst;
    for (int i = blockIdx.x * blockDim.x + threadIdx.x; i < n4; i += stride) {
        const float4 v = ((const float4*)src)[i];
        d2[2 * i]     = __floats2bfloat162_rn(v.x, v.y);
        d2[2 * i + 1] = __floats2bfloat162_rn(v.z, v.w);
    }
}

// ---------------- bf16 GEMM (512 threads, 16 warps, 4-stage cp.async) ----------------
__global__ __launch_bounds__(512, 1) void gemm_bf16_bias(
    const __nv_bfloat16* __restrict__ A, const __nv_bfloat16* __restrict__ Bw,
    const float* __restrict__ b1, const float* __restrict__ b2,
    float* __restrict__ C, int M, int N, int K)
{
    constexpr int BM = 128, BN = 128, BK = 32;
    constexpr int LDA = BK + 8;
    constexpr int ST  = 4;
    extern __shared__ __nv_bfloat16 gsm[];
    __nv_bfloat16* As = gsm;
    __nv_bfloat16* Bs = gsm + ST * BM * LDA;

    const int tid  = threadIdx.x;
    const int lane = tid & 31;
    const int warp = tid >> 5;     // 0..15
    const int wm   = warp & 3;
    const int wn   = warp >> 2;    // 0..3

    const long bm = (long)blockIdx.y * BM;
    const long bn = (long)blockIdx.x * BN;

    const uint32_t aBase = (uint32_t)__cvta_generic_to_shared(As);
    const uint32_t bBase = (uint32_t)__cvta_generic_to_shared(Bs);

    const int cr = tid >> 2;          // 0..127
    const int cs = (tid & 3) * 8;

    auto issue = [&](int st, int k0) {
        cp_async16(aBase + (uint32_t)(st * BM * LDA + cr * LDA + cs) * 2,
                   A + (size_t)(bm + cr) * K + k0 + cs);
        cp_async16(bBase + (uint32_t)(st * BN * LDA + cr * LDA + cs) * 2,
                   Bw + (size_t)(bn + cr) * K + k0 + cs);
    };

    const int KT = K / BK;

    issue(0, 0);
    asm volatile("cp.async.commit_group;");
    issue(1, BK);
    asm volatile("cp.async.commit_group;");
    issue(2, 2 * BK);
    asm volatile("cp.async.commit_group;");

    float acc[2][4][4];
#pragma unroll
    for (int mf = 0; mf < 2; ++mf)
#pragma unroll
        for (int nt = 0; nt < 4; ++nt)
#pragma unroll
            for (int q = 0; q < 4; ++q) acc[mf][nt][q] = 0.0f;

    const int aRow  = wm * 32 + (lane & 15);
    const int aColH = (lane >> 4) << 3;
    const int bRow  = wn * 32 + (((lane >> 4) & 1) << 3) + (lane & 7);
    const int bColH = ((lane >> 3) & 1) << 3;

    for (int kt = 0; kt < KT; ++kt) {
        asm volatile("cp.async.wait_group 2;");
        __syncthreads();
        if (kt + 3 < KT) issue((kt + 3) & (ST - 1), (kt + 3) * BK);
        asm volatile("cp.async.commit_group;");

        const int st = kt & (ST - 1);
        const uint32_t aS = aBase + (uint32_t)(st * BM * LDA) * 2;
        const uint32_t bS = bBase + (uint32_t)(st * BN * LDA) * 2;

#pragma unroll
        for (int kf = 0; kf < 2; ++kf) {
            const int k0 = kf * 16;
            uint32_t afr[2][4];
#pragma unroll
            for (int mf = 0; mf < 2; ++mf)
                ldsm_x4(afr[mf], aS + (uint32_t)((aRow + mf * 16) * LDA + k0 + aColH) * 2);
            uint32_t bfr[2][4];
#pragma unroll
            for (int np = 0; np < 2; ++np)
                ldsm_x4(bfr[np], bS + (uint32_t)((bRow + np * 16) * LDA + k0 + bColH) * 2);
#pragma unroll
            for (int mf = 0; mf < 2; ++mf)
#pragma unroll
                for (int nt = 0; nt < 4; ++nt)
                    mma_bf16(acc[mf][nt], afr[mf], &bfr[nt >> 1][(nt & 1) * 2]);
        }
    }

#pragma unroll
    for (int mf = 0; mf < 2; ++mf) {
#pragma unroll
        for (int nt = 0; nt < 4; ++nt) {
            const long r0 = bm + wm * 32 + mf * 16 + (lane >> 2);
            const long c0 = bn + wn * 32 + nt * 8 + 2 * (lane & 3);
            const float bias0 = b1[c0] + b2[c0];
            const float bias1 = b1[c0 + 1] + b2[c0 + 1];
            C[r0 * N + c0]           = acc[mf][nt][0] + bias0;
            C[r0 * N + c0 + 1]       = acc[mf][nt][1] + bias1;
            C[(r0 + 8) * N + c0]     = acc[mf][nt][2] + bias0;
            C[(r0 + 8) * N + c0 + 1] = acc[mf][nt][3] + bias1;
        }
    }
}

// ---------------- fused 3-layer pipelined LSTM, warp-granular dataflow sync -----------
// ROLE: 1/2/3. H hidden, KP proj input (0 => xg in gmem), HC units per CTA.
// Each WARP waits (lane-parallel acquire-poll + ballot) only on the producer CTAs
// whose h-units fall in its k-slice, then proceeds straight to ldcg+mma.
template <int ROLE, int H, int KP, int HC, int FIRST, bool LAST_ONLY>
__device__ __forceinline__ void lstm_role(
    char* dyn,
    const float* __restrict__ xg,
    const float* __restrict__ Wih,
    const float* __restrict__ Whh,
    const float* __restrict__ bih,
    const float* __restrict__ bhh,
    const uint32_t* __restrict__ ringP, int strideP,
    uint32_t* __restrict__ ringR, int strideR,
    float* __restrict__ hlast,
    unsigned* __restrict__ flags,
    int ctaLocal, int myflag)
{
    constexpr int COLS = 4 * HC;
    constexpr int GSW  = COLS + 2;
    constexpr int NT   = COLS / 8;            // n-tiles of 8
    constexpr int NTG  = NT / 4;              // n-groups (warp covers 4 nt)
    constexpr int KSN  = 4 / NTG;             // k-slice count
    constexpr int KB_P = (KP > 0) ? KP / 16 : 0;
    constexpr int KBT  = KB_P + H / 16;       // total k16 blocks
    constexpr int KS   = KBT / KSN;           // kbs per warp
    constexpr int EPT  = HC / 8;              // elements per thread (1 or 2)
    static_assert(KS * KSN == KBT, "k split");
    static_assert(NTG * 4 == NT, "n split");

    float* gS = (float*)dyn;                  // KSN slabs * 64 * GSW

    const int tid  = threadIdx.x;
    const int lane = tid & 31;
    const int w    = tid >> 5;
    const int grp  = lane >> 2;
    const int th4  = lane & 3;
    const int h0   = ctaLocal * HC;

    // ---- warp decomposition ----
    const int mi    = w & 3;
    const int wr    = w >> 2;               // 0..3
    const int ks    = wr & (KSN - 1);
    const int ntg_i = wr / KSN;

    // ---- per-lane wait assignment: (flag index, threshold offset from s) ----
    // ROLE1 (KSN=2, KS=8): producers = L1 CTAs [ks*8, ks*8+8); backpressure L2 >= s-6
    // ROLE2 (KSN=4, KS=6): kb<16 -> L1 CTA kb; kb>=16 -> L2 CTAs 2(kb-16)+{0,1};
    //                      backpressure L3 >= s-6
    // ROLE3 (KSN=2, KS=6): kb<8 -> L2 CTAs 2kb+{0,1}; kb>=8 -> L3 CTA (kb-8)
    int fIdx = -1, fOff = 0;
    if (ROLE == 1) {
        if (lane < 8)        { fIdx = ks * 8 + lane;  fOff = 0;  }
        else if (lane < 24)  { fIdx = 16 + (lane - 8); fOff = -6; }
    } else if (ROLE == 2) {
        if (lane < 12) {
            const int q = lane >> 1, r = lane & 1;
            const int kb = ks * 6 + q;
            fIdx = (kb < 16) ? kb : (16 + 2 * (kb - 16) + r);
            fOff = 0;
        } else if (lane < 16) { fIdx = 32 + (lane - 12); fOff = -6; }
    } else {
        if (lane < 12) {
            const int q = lane >> 1, r = lane & 1;
            const int kb = ks * 6 + q;
            fIdx = (kb < 8) ? (16 + 2 * kb + r) : (32 + (kb - 8));
            fOff = 0;
        }
    }
    unsigned* const fPtr = (fIdx >= 0) ? (flags + fIdx * 32) : flags;

    // ---- build weight B fragments in registers (once) ----
    uint32_t bw[KS][4][2];
    {
        const int colb = lane >> 2;          // 0..7
        const int kk0  = (lane & 3) * 2;
#pragma unroll
        for (int q = 0; q < KS; ++q) {
            const int kbg = ks * KS + q;
#pragma unroll
            for (int nip = 0; nip < 4; ++nip) {
                const int c = (ntg_i * 4 + nip) * 8 + colb;   // 0..COLS-1
                const int g = c / HC, u = c % HC;
                const int row = g * H + h0 + u;
#pragma unroll
                for (int j = 0; j < 2; ++j) {
                    const int k = kbg * 16 + kk0 + j * 8;
                    float w0, w1;
                    if (KP > 0 && k < KP) {
                        const float* p = Wih + (size_t)row * KP + k;
                        w0 = p[0]; w1 = p[1];
                    } else {
                        const float* p = Whh + (size_t)row * H + (k - KP);
                        w0 = p[0]; w1 = p[1];
                    }
                    bw[q][nip][j] = pack_h2(w0, w1);
                }
            }
        }
    }

    // ---- elementwise ownership: thread -> (batch b, EPT units) ----
    const int b  = tid >> 3;                 // 0..63
    const int j0 = (tid & 7) * EPT;          // first unit index

    float cst[EPT];
    float xr[EPT][4];
    float bias[EPT][4];
#pragma unroll
    for (int e = 0; e < EPT; ++e) {
        cst[e] = 0.0f;
        const int kme = h0 + j0 + e;
        if (KP == 0) {
            const float* xp = xg + ((size_t)b * TT) * (4 * H) + kme;
#pragma unroll
            for (int g = 0; g < 4; ++g) xr[e][g] = xp[(size_t)g * H];
        } else {
#pragma unroll
            for (int g = 0; g < 4; ++g) {
                const int r = g * H + kme;
                bias[e][g] = bih[r] + bhh[r];
            }
        }
    }

    // ---- output fragment index (A-fragment layout of my h values) ----
    const int mib   = b >> 4;
    const int lanew = (b & 7) * 4 + ((j0 & 7) >> 1);   // j0 even when EPT=2
    const int out_u32 = (HC == 16)
        ? (ctaLocal * 512 + (mib * 32 + lanew) * 4 + ((j0 >> 3) & 1) * 2 + ((b >> 3) & 1))
        : ((ctaLocal >> 1) * 512 + (mib * 32 + lanew) * 4 + (ctaLocal & 1) * 2 + ((b >> 3) & 1));

    __syncthreads();

    for (int s = 0; s < TOTS; ++s) {
        const int t = s - FIRST;
        const bool active = (t >= 0) && (t < TT);

        if (active) {
            // ---- warp-granular dataflow wait (lane-parallel poll + ballot) ----
            {
                const int thr = s + fOff;
                bool ok = (fIdx < 0) || (thr <= 0);
                const unsigned utg = (unsigned)thr;
                while (!__all_sync(0xffffffffu, ok)) {
                    if (!ok) {
                        unsigned v;
                        asm volatile("ld.acquire.gpu.global.u32 %0, [%1];"
                                     : "=r"(v) : "l"(fPtr) : "memory");
                        ok = (v >= utg);
                    }
                }
            }

            // ---- mma: A fragments loaded directly from ring buffers (L2) ----
            const uint32_t* srcP = (KP > 0) ? (ringP + (size_t)(t & (RING - 1)) * strideP)
                                            : (const uint32_t*)0;
            const uint32_t* srcR = ringR + (size_t)((t - 1) & (RING - 1)) * strideR;

            float4 avv[KS];
#pragma unroll
            for (int q = 0; q < KS; ++q) {
                const int kb = ks * KS + q;
                const uint32_t* p = (KP > 0 && kb < KB_P)
                                        ? (srcP + ((size_t)(kb * 4 + mi) * 32 + lane) * 4)
                                        : (srcR + ((size_t)((kb - KB_P) * 4 + mi) * 32 + lane) * 4);
                avv[q] = ldcg4(p);
            }

            float acc[4][4];
#pragma unroll
            for (int nip = 0; nip < 4; ++nip)
#pragma unroll
                for (int q = 0; q < 4; ++q) acc[nip][q] = 0.0f;

#pragma unroll
            for (int q = 0; q < KS; ++q) {
                const uint32_t* au = (const uint32_t*)&avv[q];
#pragma unroll
                for (int nip = 0; nip < 4; ++nip)
                    mma_f16(acc[nip], au, bw[q][nip]);
            }

            float* gr = gS + ks * (64 * GSW) + (mi * 16 + grp) * GSW + 2 * th4;
#pragma unroll
            for (int nip = 0; nip < 4; ++nip) {
                const int cc = (ntg_i * 4 + nip) * 8;
                gr[cc]               = acc[nip][0];
                gr[cc + 1]           = acc[nip][1];
                gr[8 * GSW + cc]     = acc[nip][2];
                gr[8 * GSW + cc + 1] = acc[nip][3];
            }
        }
        __syncthreads();

        // ---- activations + direct STG of h into ring (A-fragment layout) ----
        if (active) {
            uint32_t* dstR = ringR + (size_t)(t & (RING - 1)) * strideR;
            float hv[EPT];
#pragma unroll
            for (int e = 0; e < EPT; ++e) {
                const int jj  = j0 + e;
                float pi, pf, pg, po;
                if (KP == 0) { pi = xr[e][0]; pf = xr[e][1]; pg = xr[e][2]; po = xr[e][3]; }
                else         { pi = bias[e][0]; pf = bias[e][1]; pg = bias[e][2]; po = bias[e][3]; }
#pragma unroll
                for (int sl = 0; sl < KSN; ++sl) {
                    const float* row = gS + sl * (64 * GSW) + b * GSW;
                    pi += row[jj];
                    pf += row[HC + jj];
                    pg += row[2 * HC + jj];
                    po += row[3 * HC + jj];
                }
                const float iv = fast_sig(pi), fv = fast_sig(pf);
                const float gv = fast_tanh(pg), ov = fast_sig(po);
                cst[e] = fv * cst[e] + iv * gv;
                hv[e] = ov * fast_tanh(cst[e]);

                if (LAST_ONLY && t == TT - 1)
                    hlast[(size_t)b * H + h0 + jj] = hv[e];

                if (KP == 0 && t + 1 < TT) {
                    const float* xp = xg + ((size_t)b * TT + (t + 1)) * (4 * H) + h0 + jj;
#pragma unroll
                    for (int g = 0; g < 4; ++g) xr[e][g] = xp[(size_t)g * H];
                }
            }
            if (HC == 16) {
                dstR[out_u32] = pack_h2(hv[0], hv[1]);
            } else {
                ((__half*)dstR)[out_u32 * 2 + (j0 & 1)] = __float2half(hv[0]);
            }
        }
        __syncthreads();   // order STGs into CTA causality before the release

        // ---- release my flag (completed global step s) ----
        if (tid == 0) {
            asm volatile("st.release.gpu.global.u32 [%0], %1;"
                         :: "l"(flags + myflag * 32), "r"((unsigned)(s + 1)) : "memory");
        }
    }
}

__global__ __launch_bounds__(512, 1) void lstm_fused(
    const float* __restrict__ xg1,
    const float* __restrict__ Whh1,
    const float* __restrict__ Wih2, const float* __restrict__ Whh2,
    const float* __restrict__ bih2, const float* __restrict__ bhh2,
    const float* __restrict__ Wih3, const float* __restrict__ Whh3,
    const float* __restrict__ bih3, const float* __restrict__ bhh3,
    float* __restrict__ h3out, unsigned* __restrict__ flags)
{
    extern __shared__ char dynls[];
    const int cb = blockIdx.x;
    if (cb < 16) {
        lstm_role<1, H1, 0, 16, 0, false>(dynls, xg1, nullptr, Whh1, nullptr, nullptr,
                                          nullptr, 0, (uint32_t*)g_b1, 8192, nullptr,
                                          flags, cb, cb);
    } else if (cb < 32) {
        lstm_role<2, H2, H1, 8, 1, false>(dynls, nullptr, Wih2, Whh2, bih2, bhh2,
                                          (const uint32_t*)g_b1, 8192, (uint32_t*)g_b2, 4096,
                                          nullptr, flags, cb - 16, cb);
    } else {
        lstm_role<3, H3, H2, 16, 2, true>(dynls, nullptr, Wih3, Whh3, bih3, bhh3,
                                          (const uint32_t*)g_b2, 4096, (uint32_t*)g_b3, 2048,
                                          h3out, flags, cb - 32, cb);
    }
}

// ---------------- head: deep/wide/concat/output (256 threads) ----------------
__global__ __launch_bounds__(256) void head_kernel(
    const float* __restrict__ x,
    const float* __restrict__ h3last,
    const float* __restrict__ Wd, const float* __restrict__ bd,
    const float* __restrict__ Ww, const float* __restrict__ bw,
    const float* __restrict__ Wo, const float* __restrict__ bo,
    float* __restrict__ out)
{
    const int bidx = blockIdx.x;
    const int j = threadIdx.x & 31;
    const int s = threadIdx.x >> 5;
    __shared__ float red[8][33];

    const float* xrow = x + ((size_t)bidx * TT + (TT - 1)) * DD;
    const float* wwr = Ww + (size_t)j * DD;
    float acc = 0.0f;
    const int k0 = s * (DD / 8);
#pragma unroll 4
    for (int k = k0; k < k0 + DD / 8; k += 4) {
        const float4 xv = *(const float4*)&xrow[k];
        const float4 wv = *(const float4*)&wwr[k];
        acc = fmaf(xv.x, wv.x, acc);
        acc = fmaf(xv.y, wv.y, acc);
        acc = fmaf(xv.z, wv.z, acc);
        acc = fmaf(xv.w, wv.w, acc);
    }
    red[s][j] = acc;
    __syncthreads();

    if (s == 0) {
        float wide = bw[j];
#pragma unroll
        for (int q = 0; q < 8; ++q) wide += red[q][j];
        wide = fmaxf(wide, 0.0f);

        const float* hrow = h3last + (size_t)bidx * H3;
        const float* wdr = Wd + (size_t)j * H3;
        float deep = bd[j];
#pragma unroll
        for (int k = 0; k < H3; ++k) deep = fmaf(hrow[k], wdr[k], deep);
        deep = fmaxf(deep, 0.0f);

        float v = deep * Wo[j] + wide * Wo[32 + j];
#pragma unroll
        for (int off = 16; off > 0; off >>= 1)
            v += __shfl_xor_sync(0xffffffffu, v, off);
        if (j == 0) out[bidx] = v + bo[0];
    }
}

// ---------------- launch ----------------
extern "C" void kernel_launch(void* const* d_in, const int* in_sizes, int n_in,
                              void* d_out, int out_size) {
    const float* x    = (const float*)d_in[0];
    const float* Wih1 = (const float*)d_in[1];
    const float* Whh1 = (const float*)d_in[2];
    const float* bih1 = (const float*)d_in[3];
    const float* bhh1 = (const float*)d_in[4];
    const float* Wih2 = (const float*)d_in[5];
    const float* Whh2 = (const float*)d_in[6];
    const float* bih2 = (const float*)d_in[7];
    const float* bhh2 = (const float*)d_in[8];
    const float* Wih3 = (const float*)d_in[9];
    const float* Whh3 = (const float*)d_in[10];
    const float* bih3 = (const float*)d_in[11];
    const float* bhh3 = (const float*)d_in[12];
    const float* Wd   = (const float*)d_in[13];
    const float* bd   = (const float*)d_in[14];
    const float* Ww   = (const float*)d_in[15];
    const float* bw   = (const float*)d_in[16];
    const float* Wo   = (const float*)d_in[17];
    const float* bo   = (const float*)d_in[18];
    float* out = (float*)d_out;

    float *xg1, *h3;
    __nv_bfloat16 *xbf, *W1bf;
    unsigned* flags;
    cudaGetSymbolAddress((void**)&xg1,   g_xg1);
    cudaGetSymbolAddress((void**)&h3,    g_h3);
    cudaGetSymbolAddress((void**)&xbf,   g_xbf);
    cudaGetSymbolAddress((void**)&W1bf,  g_W1bf);
    cudaGetSymbolAddress((void**)&flags, g_flags);

    const int M = BB * TT;  // 32768

    prep_zero<<<120, 512>>>();

    // convert x and Wih1 to bf16 for the big GEMM
    f2bf_kernel<<<4096, 256>>>(x,    xbf,  (BB * TT * DD) / 4);
    f2bf_kernel<<<512,  256>>>(Wih1, W1bf, (4 * H1 * DD) / 4);

    // layer-1 input projection: xg1 = x @ Wih1^T + bih1 + bhh1
    {
        const int gsmem = 4 * (128 + 128) * 40 * 2;  // 81920 B
        cudaFuncSetAttribute(gemm_bf16_bias, cudaFuncAttributeMaxDynamicSharedMemorySize, gsmem);
        dim3 grid((4 * H1) / 128, M / 128);
        gemm_bf16_bias<<<grid, 512, gsmem>>>(xbf, W1bf, bih1, bhh1, xg1, M, 4 * H1, DD);
    }

    // fused pipelined 3-layer recurrence (36 CTAs, warp-granular dataflow sync)
    {
        // max over roles: L2 = 4*64*34*4 = 34816 B
        const int dynBytes = 36864;
        cudaFuncSetAttribute(lstm_fused, cudaFuncAttributeMaxDynamicSharedMemorySize, dynBytes);
        lstm_fused<<<NCTA_ALL, 512, dynBytes>>>(xg1, Whh1,
                                                Wih2, Whh2, bih2, bhh2,
                                                Wih3, Whh3, bih3, bhh3,
                                                h3, flags);
    }

    // head
    head_kernel<<<BB, 256>>>(x, h3, Wd, bd, Ww, bw, Wo, bo, out);

    (void)in_sizes; (void)n_in; (void)out_size;
}

// round 13
// speedup vs baseline: 1.9239x; 1.1079x over previous
#include <cuda_runtime.h>
#include <cuda_bf16.h>
#include <cuda_fp16.h>
#include <cstdint>
#include <math.h>

// Problem dims (fixed by the reference)
#define BB 64
#define TT 512
#define DD 2048
#define H1 256
#define H2 128
#define H3 64

#define NCTA_LSTM 36     // 16 (L1) + 16 (L2) + 4 (L3)
#define NCTA_GEMM 2048   // 8 n-tiles x 256 m-tiles
#define TOTS (TT + 2)
#define RING 8

// ---------------- scratch (static device buffers; no allocation) ----------------
__device__ __align__(16) float g_xg1[(size_t)BB * TT * 4 * H1];   // 32768 x 1024
__device__ __align__(16) __nv_bfloat16 g_xbf[(size_t)BB * TT * DD];
__device__ __align__(16) __nv_bfloat16 g_W1bf[4 * H1 * DD];
__device__ __align__(16) float g_h3[BB * H3];         // layer-3 last h (fp32)
// h ring buffers (fp16 mma A-fragment layout, u32 units), 8 deep
__device__ __align__(16) uint32_t g_b1[RING][8192];   // h1: 16 kb x 512 u32
__device__ __align__(16) uint32_t g_b2[RING][4096];   // h2:  8 kb x 512
__device__ __align__(16) uint32_t g_b3[RING][2048];   // h3:  4 kb x 512
__device__ unsigned g_flags[NCTA_LSTM * 32];          // one flag per lstm CTA, 128B apart
__device__ unsigned g_xgcnt[4 * 32];                  // per-t-chunk gemm tile counters

// ---------------- helpers ----------------
__device__ __forceinline__ void mma_bf16(float* c, const uint32_t* a, const uint32_t* b) {
    asm volatile(
        "mma.sync.aligned.m16n8k16.row.col.f32.bf16.bf16.f32 "
        "{%0,%1,%2,%3}, {%4,%5,%6,%7}, {%8,%9}, {%0,%1,%2,%3};"
        : "+f"(c[0]), "+f"(c[1]), "+f"(c[2]), "+f"(c[3])
        : "r"(a[0]), "r"(a[1]), "r"(a[2]), "r"(a[3]), "r"(b[0]), "r"(b[1]));
}

__device__ __forceinline__ void mma_f16(float* c, const uint32_t* a, const uint32_t* b) {
    asm volatile(
        "mma.sync.aligned.m16n8k16.row.col.f32.f16.f16.f32 "
        "{%0,%1,%2,%3}, {%4,%5,%6,%7}, {%8,%9}, {%0,%1,%2,%3};"
        : "+f"(c[0]), "+f"(c[1]), "+f"(c[2]), "+f"(c[3])
        : "r"(a[0]), "r"(a[1]), "r"(a[2]), "r"(a[3]), "r"(b[0]), "r"(b[1]));
}

__device__ __forceinline__ void ldsm_x4(uint32_t* r, uint32_t addr) {
    asm volatile("ldmatrix.sync.aligned.m8n8.x4.shared.b16 {%0,%1,%2,%3}, [%4];"
                 : "=r"(r[0]), "=r"(r[1]), "=r"(r[2]), "=r"(r[3]) : "r"(addr));
}

__device__ __forceinline__ void cp_async16(uint32_t smem, const void* g) {
    asm volatile("cp.async.cg.shared.global [%0], [%1], 16;" :: "r"(smem), "l"(g));
}

__device__ __forceinline__ float4 ldcg4(const uint32_t* p) {
    float4 v;
    asm volatile("ld.global.cg.v4.f32 {%0,%1,%2,%3}, [%4];"
                 : "=f"(v.x), "=f"(v.y), "=f"(v.z), "=f"(v.w) : "l"(p));
    return v;
}

__device__ __forceinline__ float rcp_(float x) {
    float r;
    asm("rcp.approx.f32 %0, %1;" : "=f"(r) : "f"(x));
    return r;
}
__device__ __forceinline__ float fast_sig(float x) { return rcp_(1.0f + __expf(-x)); }
__device__ __forceinline__ float fast_tanh(float x) { return 2.0f * rcp_(1.0f + __expf(-2.0f * x)) - 1.0f; }

__device__ __forceinline__ uint32_t pack_h2(float a, float b) {
    __half2 h = __floats2half2_rn(a, b);
    return *reinterpret_cast<uint32_t*>(&h);
}

__device__ __forceinline__ unsigned ld_acq(const unsigned* p) {
    unsigned v;
    asm volatile("ld.acquire.gpu.global.u32 %0, [%1];" : "=r"(v) : "l"(p) : "memory");
    return v;
}

// ---------------- prep: zero flags/counters + h ring buffers (every replay) ----------
__global__ void prep_zero() {
    const int i = blockIdx.x * blockDim.x + threadIdx.x;
    if (i < NCTA_LSTM * 32) g_flags[i] = 0u;
    if (i < 4 * 32) g_xgcnt[i] = 0u;
    const int n1 = RING * 8192, n2 = RING * 4096, n3 = RING * 2048;
    uint32_t* p1 = (uint32_t*)g_b1;
    uint32_t* p2 = (uint32_t*)g_b2;
    uint32_t* p3 = (uint32_t*)g_b3;
    const int stride = gridDim.x * blockDim.x;
    for (int k = i; k < n1; k += stride) p1[k] = 0u;
    for (int k = i; k < n2; k += stride) p2[k] = 0u;
    for (int k = i; k < n3; k += stride) p3[k] = 0u;
}

// ---------------- fp32 -> bf16 conversion (vectorized) ----------------
__global__ void f2bf_kernel(const float* __restrict__ src, __nv_bfloat16* __restrict__ dst, int n4) {
    const int stride = gridDim.x * blockDim.x;
    __nv_bfloat162* d2 = (__nv_bfloat162*)dst;
    for (int i = blockIdx.x * blockDim.x + threadIdx.x; i < n4; i += stride) {
        const float4 v = ((const float4*)src)[i];
        d2[2 * i]     = __floats2bfloat162_rn(v.x, v.y);
        d2[2 * i + 1] = __floats2bfloat162_rn(v.z, v.w);
    }
}

// ---------------- bf16 GEMM tile body (512 threads, 4-stage cp.async) ----------------
// Computes one 128x128 tile of xg1 = x @ Wih1^T + bias; tiles ordered so that
// t-chunk (slowest index) completes early; releases g_xgcnt[tc] when done.
__device__ __forceinline__ void gemm_body(
    char* dyn, int gb,
    const __nv_bfloat16* __restrict__ A, const __nv_bfloat16* __restrict__ Bw,
    const float* __restrict__ b1, const float* __restrict__ b2,
    float* __restrict__ C, unsigned* __restrict__ xgcnt)
{
    constexpr int BM = 128, BN = 128, BK = 32;
    constexpr int LDA = BK + 8;
    constexpr int ST  = 4;
    constexpr int K   = DD;
    constexpr int N   = 4 * H1;
    __nv_bfloat16* As = (__nv_bfloat16*)dyn;
    __nv_bfloat16* Bs = As + ST * BM * LDA;

    const int tid  = threadIdx.x;
    const int lane = tid & 31;
    const int warp = tid >> 5;
    const int wm   = warp & 3;
    const int wn   = warp >> 2;

    // tile mapping: nx fast, batch mid, t-chunk slow (so chunk 0 tiles run first)
    const int nx    = gb & 7;
    const int myIdx = gb >> 3;           // 0..255
    const int tc    = myIdx >> 6;        // t-chunk 0..3
    const int bbat  = myIdx & 63;        // batch
    const long bm = (long)bbat * TT + (long)tc * 128;
    const long bn = (long)nx * BN;

    const uint32_t aBase = (uint32_t)__cvta_generic_to_shared(As);
    const uint32_t bBase = (uint32_t)__cvta_generic_to_shared(Bs);

    const int cr = tid >> 2;
    const int cs = (tid & 3) * 8;

    auto issue = [&](int st, int k0) {
        cp_async16(aBase + (uint32_t)(st * BM * LDA + cr * LDA + cs) * 2,
                   A + (size_t)(bm + cr) * K + k0 + cs);
        cp_async16(bBase + (uint32_t)(st * BN * LDA + cr * LDA + cs) * 2,
                   Bw + (size_t)(bn + cr) * K + k0 + cs);
    };

    const int KT = K / BK;

    issue(0, 0);
    asm volatile("cp.async.commit_group;");
    issue(1, BK);
    asm volatile("cp.async.commit_group;");
    issue(2, 2 * BK);
    asm volatile("cp.async.commit_group;");

    float acc[2][4][4];
#pragma unroll
    for (int mf = 0; mf < 2; ++mf)
#pragma unroll
        for (int nt = 0; nt < 4; ++nt)
#pragma unroll
            for (int q = 0; q < 4; ++q) acc[mf][nt][q] = 0.0f;

    const int aRow  = wm * 32 + (lane & 15);
    const int aColH = (lane >> 4) << 3;
    const int bRow  = wn * 32 + (((lane >> 4) & 1) << 3) + (lane & 7);
    const int bColH = ((lane >> 3) & 1) << 3;

    for (int kt = 0; kt < KT; ++kt) {
        asm volatile("cp.async.wait_group 2;");
        __syncthreads();
        if (kt + 3 < KT) issue((kt + 3) & (ST - 1), (kt + 3) * BK);
        asm volatile("cp.async.commit_group;");

        const int st = kt & (ST - 1);
        const uint32_t aS = aBase + (uint32_t)(st * BM * LDA) * 2;
        const uint32_t bS = bBase + (uint32_t)(st * BN * LDA) * 2;

#pragma unroll
        for (int kf = 0; kf < 2; ++kf) {
            const int k0 = kf * 16;
            uint32_t afr[2][4];
#pragma unroll
            for (int mf = 0; mf < 2; ++mf)
                ldsm_x4(afr[mf], aS + (uint32_t)((aRow + mf * 16) * LDA + k0 + aColH) * 2);
            uint32_t bfr[2][4];
#pragma unroll
            for (int np = 0; np < 2; ++np)
                ldsm_x4(bfr[np], bS + (uint32_t)((bRow + np * 16) * LDA + k0 + bColH) * 2);
#pragma unroll
            for (int mf = 0; mf < 2; ++mf)
#pragma unroll
                for (int nt = 0; nt < 4; ++nt)
                    mma_bf16(acc[mf][nt], afr[mf], &bfr[nt >> 1][(nt & 1) * 2]);
        }
    }

#pragma unroll
    for (int mf = 0; mf < 2; ++mf) {
#pragma unroll
        for (int nt = 0; nt < 4; ++nt) {
            const long r0 = bm + wm * 32 + mf * 16 + (lane >> 2);
            const long c0 = bn + wn * 32 + nt * 8 + 2 * (lane & 3);
            const float bias0 = b1[c0] + b2[c0];
            const float bias1 = b1[c0 + 1] + b2[c0 + 1];
            C[r0 * N + c0]           = acc[mf][nt][0] + bias0;
            C[r0 * N + c0 + 1]       = acc[mf][nt][1] + bias1;
            C[(r0 + 8) * N + c0]     = acc[mf][nt][2] + bias0;
            C[(r0 + 8) * N + c0 + 1] = acc[mf][nt][3] + bias1;
        }
    }

    // release: this tile of t-chunk tc is complete
    __syncthreads();
    if (tid == 0) {
        asm volatile("red.release.gpu.global.add.u32 [%0], 1;"
                     :: "l"(xgcnt + tc * 32) : "memory");
    }
}

// ---------------- fused 3-layer pipelined LSTM, warp-granular dataflow sync -----------
template <int ROLE, int H, int KP, int HC, int FIRST, bool LAST_ONLY>
__device__ __forceinline__ void lstm_role(
    char* dyn,
    const float* __restrict__ xg,
    const float* __restrict__ Wih,
    const float* __restrict__ Whh,
    const float* __restrict__ bih,
    const float* __restrict__ bhh,
    const uint32_t* __restrict__ ringP, int strideP,
    uint32_t* __restrict__ ringR, int strideR,
    float* __restrict__ hlast,
    unsigned* __restrict__ flags,
    unsigned* __restrict__ xgcnt,
    int ctaLocal, int myflag)
{
    constexpr int COLS = 4 * HC;
    constexpr int GSW  = COLS + 2;
    constexpr int NT   = COLS / 8;
    constexpr int NTG  = NT / 4;
    constexpr int KSN  = 4 / NTG;
    constexpr int KB_P = (KP > 0) ? KP / 16 : 0;
    constexpr int KBT  = KB_P + H / 16;
    constexpr int KS   = KBT / KSN;
    constexpr int EPT  = HC / 8;
    static_assert(KS * KSN == KBT, "k split");
    static_assert(NTG * 4 == NT, "n split");

    float* gS = (float*)dyn;

    const int tid  = threadIdx.x;
    const int lane = tid & 31;
    const int w    = tid >> 5;
    const int grp  = lane >> 2;
    const int th4  = lane & 3;
    const int h0   = ctaLocal * HC;

    const int mi    = w & 3;
    const int wr    = w >> 2;
    const int ks    = wr & (KSN - 1);
    const int ntg_i = wr / KSN;

    int fIdx = -1, fOff = 0;
    if (ROLE == 1) {
        if (lane < 8)        { fIdx = ks * 8 + lane;  fOff = 0;  }
        else if (lane < 24)  { fIdx = 16 + (lane - 8); fOff = -6; }
    } else if (ROLE == 2) {
        if (lane < 12) {
            const int q = lane >> 1, r = lane & 1;
            const int kb = ks * 6 + q;
            fIdx = (kb < 16) ? kb : (16 + 2 * (kb - 16) + r);
            fOff = 0;
        } else if (lane < 16) { fIdx = 32 + (lane - 12); fOff = -6; }
    } else {
        if (lane < 12) {
            const int q = lane >> 1, r = lane & 1;
            const int kb = ks * 6 + q;
            fIdx = (kb < 8) ? (16 + 2 * kb + r) : (32 + (kb - 8));
            fOff = 0;
        }
    }
    unsigned* const fPtr = (fIdx >= 0) ? (flags + fIdx * 32) : flags;

    uint32_t bw[KS][4][2];
    {
        const int colb = lane >> 2;
        const int kk0  = (lane & 3) * 2;
#pragma unroll
        for (int q = 0; q < KS; ++q) {
            const int kbg = ks * KS + q;
#pragma unroll
            for (int nip = 0; nip < 4; ++nip) {
                const int c = (ntg_i * 4 + nip) * 8 + colb;
                const int g = c / HC, u = c % HC;
                const int row = g * H + h0 + u;
#pragma unroll
                for (int j = 0; j < 2; ++j) {
                    const int k = kbg * 16 + kk0 + j * 8;
                    float w0, w1;
                    if (KP > 0 && k < KP) {
                        const float* p = Wih + (size_t)row * KP + k;
                        w0 = p[0]; w1 = p[1];
                    } else {
                        const float* p = Whh + (size_t)row * H + (k - KP);
                        w0 = p[0]; w1 = p[1];
                    }
                    bw[q][nip][j] = pack_h2(w0, w1);
                }
            }
        }
    }

    const int b  = tid >> 3;
    const int j0 = (tid & 7) * EPT;

    float cst[EPT];
    float xr[EPT][4];
    float bias[EPT][4];
#pragma unroll
    for (int e = 0; e < EPT; ++e) {
        cst[e] = 0.0f;
        if (KP > 0) {
            const int kme = h0 + j0 + e;
#pragma unroll
            for (int g = 0; g < 4; ++g) {
                const int r = g * H + kme;
                bias[e][g] = bih[r] + bhh[r];
            }
        }
    }

    // ROLE1: wait for xg t-chunk 0 before the initial prefetch of xg[t=0]
    if (KP == 0) {
        if (tid == 0) {
            while (ld_acq(xgcnt) < 512u) { }
        }
        __syncthreads();
#pragma unroll
        for (int e = 0; e < EPT; ++e) {
            const int kme = h0 + j0 + e;
            const float* xp = xg + ((size_t)b * TT) * (4 * H) + kme;
#pragma unroll
            for (int g = 0; g < 4; ++g) xr[e][g] = xp[(size_t)g * H];
        }
    }

    const int mib   = b >> 4;
    const int lanew = (b & 7) * 4 + ((j0 & 7) >> 1);
    const int out_u32 = (HC == 16)
        ? (ctaLocal * 512 + (mib * 32 + lanew) * 4 + ((j0 >> 3) & 1) * 2 + ((b >> 3) & 1))
        : ((ctaLocal >> 1) * 512 + (mib * 32 + lanew) * 4 + (ctaLocal & 1) * 2 + ((b >> 3) & 1));

    __syncthreads();

    for (int s = 0; s < TOTS; ++s) {
        const int t = s - FIRST;
        const bool active = (t >= 0) && (t < TT);

        if (active) {
            {
                const int thr = s + fOff;
                bool ok = (fIdx < 0) || (thr <= 0);
                const unsigned utg = (unsigned)thr;
                while (!__all_sync(0xffffffffu, ok)) {
                    if (!ok) {
                        ok = (ld_acq(fPtr) >= utg);
                    }
                }
            }

            // ROLE1: at t-chunk boundaries, ensure the NEXT xg chunk is ready
            // (prefetch below reads xg[t+1])
            if (KP == 0) {
                const int tn = t + 1;
                if (tn < TT && (tn & 127) == 0) {
                    if (tid == 0) {
                        unsigned* cp = xgcnt + (tn >> 7) * 32;
                        while (ld_acq(cp) < 512u) { }
                    }
                    __syncthreads();
                }
            }

            const uint32_t* srcP = (KP > 0) ? (ringP + (size_t)(t & (RING - 1)) * strideP)
                                            : (const uint32_t*)0;
            const uint32_t* srcR = ringR + (size_t)((t - 1) & (RING - 1)) * strideR;

            float4 avv[KS];
#pragma unroll
            for (int q = 0; q < KS; ++q) {
                const int kb = ks * KS + q;
                const uint32_t* p = (KP > 0 && kb < KB_P)
                                        ? (srcP + ((size_t)(kb * 4 + mi) * 32 + lane) * 4)
                                        : (srcR + ((size_t)((kb - KB_P) * 4 + mi) * 32 + lane) * 4);
                avv[q] = ldcg4(p);
            }

            float acc[4][4];
#pragma unroll
            for (int nip = 0; nip < 4; ++nip)
#pragma unroll
                for (int q = 0; q < 4; ++q) acc[nip][q] = 0.0f;

#pragma unroll
            for (int q = 0; q < KS; ++q) {
                const uint32_t* au = (const uint32_t*)&avv[q];
#pragma unroll
                for (int nip = 0; nip < 4; ++nip)
                    mma_f16(acc[nip], au, bw[q][nip]);
            }

            float* gr = gS + ks * (64 * GSW) + (mi * 16 + grp) * GSW + 2 * th4;
#pragma unroll
            for (int nip = 0; nip < 4; ++nip) {
                const int cc = (ntg_i * 4 + nip) * 8;
                gr[cc]               = acc[nip][0];
                gr[cc + 1]           = acc[nip][1];
                gr[8 * GSW + cc]     = acc[nip][2];
                gr[8 * GSW + cc + 1] = acc[nip][3];
            }
        }
        __syncthreads();

        if (active) {
            uint32_t* dstR = ringR + (size_t)(t & (RING - 1)) * strideR;
            float hv[EPT];
#pragma unroll
            for (int e = 0; e < EPT; ++e) {
                const int jj  = j0 + e;
                float pi, pf, pg, po;
                if (KP == 0) { pi = xr[e][0]; pf = xr[e][1]; pg = xr[e][2]; po = xr[e][3]; }
                else         { pi = bias[e][0]; pf = bias[e][1]; pg = bias[e][2]; po = bias[e][3]; }
#pragma unroll
                for (int sl = 0; sl < KSN; ++sl) {
                    const float* row = gS + sl * (64 * GSW) + b * GSW;
                    pi += row[jj];
                    pf += row[HC + jj];
                    pg += row[2 * HC + jj];
                    po += row[3 * HC + jj];
                }
                const float iv = fast_sig(pi), fv = fast_sig(pf);
                const float gv = fast_tanh(pg), ov = fast_sig(po);
                cst[e] = fv * cst[e] + iv * gv;
                hv[e] = ov * fast_tanh(cst[e]);

                if (LAST_ONLY && t == TT - 1)
                    hlast[(size_t)b * H + h0 + jj] = hv[e];

                if (KP == 0 && t + 1 < TT) {
                    const float* xp = xg + ((size_t)b * TT + (t + 1)) * (4 * H) + h0 + jj;
#pragma unroll
                    for (int g = 0; g < 4; ++g) xr[e][g] = xp[(size_t)g * H];
                }
            }
            if (HC == 16) {
                dstR[out_u32] = pack_h2(hv[0], hv[1]);
            } else {
                ((__half*)dstR)[out_u32 * 2 + (j0 & 1)] = __float2half(hv[0]);
            }
        }
        __syncthreads();

        if (tid == 0) {
            asm volatile("st.release.gpu.global.u32 [%0], %1;"
                         :: "l"(flags + myflag * 32), "r"((unsigned)(s + 1)) : "memory");
        }
    }
}

// ---------------- mega kernel: 36 lstm CTAs + 2048 gemm CTAs in one launch -----------
__global__ __launch_bounds__(512, 1) void mega(
    const __nv_bfloat16* __restrict__ xbf, const __nv_bfloat16* __restrict__ W1bf,
    const float* __restrict__ bih1, const float* __restrict__ bhh1,
    float* __restrict__ xg1,
    const float* __restrict__ Whh1,
    const float* __restrict__ Wih2, const float* __restrict__ Whh2,
    const float* __restrict__ bih2, const float* __restrict__ bhh2,
    const float* __restrict__ Wih3, const float* __restrict__ Whh3,
    const float* __restrict__ bih3, const float* __restrict__ bhh3,
    float* __restrict__ h3out, unsigned* __restrict__ flags,
    unsigned* __restrict__ xgcnt)
{
    extern __shared__ char dynls[];
    const int cb = blockIdx.x;
    if (cb < 16) {
        lstm_role<1, H1, 0, 16, 0, false>(dynls, xg1, nullptr, Whh1, nullptr, nullptr,
                                          nullptr, 0, (uint32_t*)g_b1, 8192, nullptr,
                                          flags, xgcnt, cb, cb);
    } else if (cb < 32) {
        lstm_role<2, H2, H1, 8, 1, false>(dynls, nullptr, Wih2, Whh2, bih2, bhh2,
                                          (const uint32_t*)g_b1, 8192, (uint32_t*)g_b2, 4096,
                                          nullptr, flags, xgcnt, cb - 16, cb);
    } else if (cb < NCTA_LSTM) {
        lstm_role<3, H3, H2, 16, 2, true>(dynls, nullptr, Wih3, Whh3, bih3, bhh3,
                                          (const uint32_t*)g_b2, 4096, (uint32_t*)g_b3, 2048,
                                          h3out, flags, xgcnt, cb - 32, cb);
    } else {
        gemm_body(dynls, cb - NCTA_LSTM, xbf, W1bf, bih1, bhh1, xg1, xgcnt);
    }
}

// ---------------- head: deep/wide/concat/output (256 threads) ----------------
__global__ __launch_bounds__(256) void head_kernel(
    const float* __restrict__ x,
    const float* __restrict__ h3last,
    const float* __restrict__ Wd, const float* __restrict__ bd,
    const float* __restrict__ Ww, const float* __restrict__ bw,
    const float* __restrict__ Wo, const float* __restrict__ bo,
    float* __restrict__ out)
{
    const int bidx = blockIdx.x;
    const int j = threadIdx.x & 31;
    const int s = threadIdx.x >> 5;
    __shared__ float red[8][33];

    const float* xrow = x + ((size_t)bidx * TT + (TT - 1)) * DD;
    const float* wwr = Ww + (size_t)j * DD;
    float acc = 0.0f;
    const int k0 = s * (DD / 8);
#pragma unroll 4
    for (int k = k0; k < k0 + DD / 8; k += 4) {
        const float4 xv = *(const float4*)&xrow[k];
        const float4 wv = *(const float4*)&wwr[k];
        acc = fmaf(xv.x, wv.x, acc);
        acc = fmaf(xv.y, wv.y, acc);
        acc = fmaf(xv.z, wv.z, acc);
        acc = fmaf(xv.w, wv.w, acc);
    }
    red[s][j] = acc;
    __syncthreads();

    if (s == 0) {
        float wide = bw[j];
#pragma unroll
        for (int q = 0; q < 8; ++q) wide += red[q][j];
        wide = fmaxf(wide, 0.0f);

        const float* hrow = h3last + (size_t)bidx * H3;
        const float* wdr = Wd + (size_t)j * H3;
        float deep = bd[j];
#pragma unroll
        for (int k = 0; k < H3; ++k) deep = fmaf(hrow[k], wdr[k], deep);
        deep = fmaxf(deep, 0.0f);

        float v = deep * Wo[j] + wide * Wo[32 + j];
#pragma unroll
        for (int off = 16; off > 0; off >>= 1)
            v += __shfl_xor_sync(0xffffffffu, v, off);
        if (j == 0) out[bidx] = v + bo[0];
    }
}

// ---------------- launch ----------------
extern "C" void kernel_launch(void* const* d_in, const int* in_sizes, int n_in,
                              void* d_out, int out_size) {
    const float* x    = (const float*)d_in[0];
    const float* Wih1 = (const float*)d_in[1];
    const float* Whh1 = (const float*)d_in[2];
    const float* bih1 = (const float*)d_in[3];
    const float* bhh1 = (const float*)d_in[4];
    const float* Wih2 = (const float*)d_in[5];
    const float* Whh2 = (const float*)d_in[6];
    const float* bih2 = (const float*)d_in[7];
    const float* bhh2 = (const float*)d_in[8];
    const float* Wih3 = (const float*)d_in[9];
    const float* Whh3 = (const float*)d_in[10];
    const float* bih3 = (const float*)d_in[11];
    const float* bhh3 = (const float*)d_in[12];
    const float* Wd   = (const float*)d_in[13];
    const float* bd   = (const float*)d_in[14];
    const float* Ww   = (const float*)d_in[15];
    const float* bw   = (const float*)d_in[16];
    const float* Wo   = (const float*)d_in[17];
    const float* bo   = (const float*)d_in[18];
    float* out = (float*)d_out;

    float *xg1, *h3;
    __nv_bfloat16 *xbf, *W1bf;
    unsigned *flags, *xgcnt;
    cudaGetSymbolAddress((void**)&xg1,   g_xg1);
    cudaGetSymbolAddress((void**)&h3,    g_h3);
    cudaGetSymbolAddress((void**)&xbf,   g_xbf);
    cudaGetSymbolAddress((void**)&W1bf,  g_W1bf);
    cudaGetSymbolAddress((void**)&flags, g_flags);
    cudaGetSymbolAddress((void**)&xgcnt, g_xgcnt);

    prep_zero<<<120, 512>>>();

    // convert x and Wih1 to bf16 for the big GEMM
    f2bf_kernel<<<4096, 256>>>(x,    xbf,  (BB * TT * DD) / 4);
    f2bf_kernel<<<512,  256>>>(Wih1, W1bf, (4 * H1 * DD) / 4);

    // mega kernel: gemm (producer, t-chunk-ordered) + 3-layer recurrence (consumer)
    {
        const int dynBytes = 4 * (128 + 128) * 40 * 2;   // 81920 (gemm need; lstm uses 34816)
        cudaFuncSetAttribute(mega, cudaFuncAttributeMaxDynamicSharedMemorySize, dynBytes);
        mega<<<NCTA_LSTM + NCTA_GEMM, 512, dynBytes>>>(
            xbf, W1bf, bih1, bhh1, xg1,
            Whh1, Wih2, Whh2, bih2, bhh2,
            Wih3, Whh3, bih3, bhh3,
            h3, flags, xgcnt);
    }

    // head
    head_kernel<<<BB, 256>>>(x, h3, Wd, bd, Ww, bw, Wo, bo, out);

    (void)in_sizes; (void)n_in; (void)out_size;
}

// round 14
// speedup vs baseline: 2.5005x; 1.2997x over previous
#include <cuda_runtime.h>
#include <cuda_bf16.h>
#include <cuda_fp16.h>
#include <cstdint>
#include <math.h>

// Problem dims (fixed by the reference)
#define BB 64
#define TT 512
#define DD 2048
#define H1 256
#define H2 128
#define H3 64

#define NCTA_LSTM 72     // 2 groups x (16 L1 + 16 L2 + 4 L3)
#define NCTA_GEMM 2048   // 8 n-tiles x 256 m-tiles
#define TOTS (TT + 2)
#define RING 8

// ---------------- scratch (static device buffers; no allocation) ----------------
__device__ __align__(16) float g_xg1[(size_t)BB * TT * 4 * H1];   // 32768 x 1024
__device__ __align__(16) __nv_bfloat16 g_xbf[(size_t)BB * TT * DD];
__device__ __align__(16) __nv_bfloat16 g_W1bf[4 * H1 * DD];
__device__ __align__(16) float g_h3[BB * H3];         // layer-3 last h (fp32)
// per-group h ring buffers (fp16 mma A-fragment layout, u32 units), 8 deep
__device__ __align__(16) uint32_t g_b1[2][RING][4096];   // h1: 16 kb x 2 mt x 128 u32
__device__ __align__(16) uint32_t g_b2[2][RING][2048];   // h2:  8 kb
__device__ __align__(16) uint32_t g_b3[2][RING][1024];   // h3:  4 kb
__device__ unsigned g_flags[2][36 * 32];              // per-group per-CTA flags, 128B apart
__device__ unsigned g_xgcnt[4 * 32];                  // per-t-chunk gemm tile counters

// ---------------- helpers ----------------
__device__ __forceinline__ void mma_bf16(float* c, const uint32_t* a, const uint32_t* b) {
    asm volatile(
        "mma.sync.aligned.m16n8k16.row.col.f32.bf16.bf16.f32 "
        "{%0,%1,%2,%3}, {%4,%5,%6,%7}, {%8,%9}, {%0,%1,%2,%3};"
        : "+f"(c[0]), "+f"(c[1]), "+f"(c[2]), "+f"(c[3])
        : "r"(a[0]), "r"(a[1]), "r"(a[2]), "r"(a[3]), "r"(b[0]), "r"(b[1]));
}

__device__ __forceinline__ void mma_f16(float* c, const uint32_t* a, const uint32_t* b) {
    asm volatile(
        "mma.sync.aligned.m16n8k16.row.col.f32.f16.f16.f32 "
        "{%0,%1,%2,%3}, {%4,%5,%6,%7}, {%8,%9}, {%0,%1,%2,%3};"
        : "+f"(c[0]), "+f"(c[1]), "+f"(c[2]), "+f"(c[3])
        : "r"(a[0]), "r"(a[1]), "r"(a[2]), "r"(a[3]), "r"(b[0]), "r"(b[1]));
}

__device__ __forceinline__ void ldsm_x4(uint32_t* r, uint32_t addr) {
    asm volatile("ldmatrix.sync.aligned.m8n8.x4.shared.b16 {%0,%1,%2,%3}, [%4];"
                 : "=r"(r[0]), "=r"(r[1]), "=r"(r[2]), "=r"(r[3]) : "r"(addr));
}

__device__ __forceinline__ void cp_async16(uint32_t smem, const void* g) {
    asm volatile("cp.async.cg.shared.global [%0], [%1], 16;" :: "r"(smem), "l"(g));
}

__device__ __forceinline__ float4 ldcg4(const uint32_t* p) {
    float4 v;
    asm volatile("ld.global.cg.v4.f32 {%0,%1,%2,%3}, [%4];"
                 : "=f"(v.x), "=f"(v.y), "=f"(v.z), "=f"(v.w) : "l"(p));
    return v;
}

__device__ __forceinline__ float rcp_(float x) {
    float r;
    asm("rcp.approx.f32 %0, %1;" : "=f"(r) : "f"(x));
    return r;
}
__device__ __forceinline__ float fast_sig(float x) { return rcp_(1.0f + __expf(-x)); }
__device__ __forceinline__ float fast_tanh(float x) { return 2.0f * rcp_(1.0f + __expf(-2.0f * x)) - 1.0f; }

__device__ __forceinline__ uint32_t pack_h2(float a, float b) {
    __half2 h = __floats2half2_rn(a, b);
    return *reinterpret_cast<uint32_t*>(&h);
}

__device__ __forceinline__ unsigned ld_acq(const unsigned* p) {
    unsigned v;
    asm volatile("ld.acquire.gpu.global.u32 %0, [%1];" : "=r"(v) : "l"(p) : "memory");
    return v;
}

// ---------------- prep: zero flags/counters + h ring buffers (every replay) ----------
__global__ void prep_zero() {
    const int i = blockIdx.x * blockDim.x + threadIdx.x;
    if (i < 2 * 36 * 32) ((unsigned*)g_flags)[i] = 0u;
    if (i < 4 * 32) g_xgcnt[i] = 0u;
    const int n1 = 2 * RING * 4096, n2 = 2 * RING * 2048, n3 = 2 * RING * 1024;
    uint32_t* p1 = (uint32_t*)g_b1;
    uint32_t* p2 = (uint32_t*)g_b2;
    uint32_t* p3 = (uint32_t*)g_b3;
    const int stride = gridDim.x * blockDim.x;
    for (int k = i; k < n1; k += stride) p1[k] = 0u;
    for (int k = i; k < n2; k += stride) p2[k] = 0u;
    for (int k = i; k < n3; k += stride) p3[k] = 0u;
}

// ---------------- fp32 -> bf16 conversion (vectorized) ----------------
__global__ void f2bf_kernel(const float* __restrict__ src, __nv_bfloat16* __restrict__ dst, int n4) {
    const int stride = gridDim.x * blockDim.x;
    __nv_bfloat162* d2 = (__nv_bfloat162*)dst;
    for (int i = blockIdx.x * blockDim.x + threadIdx.x; i < n4; i += stride) {
        const float4 v = ((const float4*)src)[i];
        d2[2 * i]     = __floats2bfloat162_rn(v.x, v.y);
        d2[2 * i + 1] = __floats2bfloat162_rn(v.z, v.w);
    }
}

// ---------------- bf16 GEMM tile body (512 threads, 4-stage cp.async) ----------------
__device__ __forceinline__ void gemm_body(
    char* dyn, int gb,
    const __nv_bfloat16* __restrict__ A, const __nv_bfloat16* __restrict__ Bw,
    const float* __restrict__ b1, const float* __restrict__ b2,
    float* __restrict__ C, unsigned* __restrict__ xgcnt)
{
    constexpr int BM = 128, BN = 128, BK = 32;
    constexpr int LDA = BK + 8;
    constexpr int ST  = 4;
    constexpr int K   = DD;
    constexpr int N   = 4 * H1;
    __nv_bfloat16* As = (__nv_bfloat16*)dyn;
    __nv_bfloat16* Bs = As + ST * BM * LDA;

    const int tid  = threadIdx.x;
    const int lane = tid & 31;
    const int warp = tid >> 5;
    const int wm   = warp & 3;
    const int wn   = warp >> 2;

    const int nx    = gb & 7;
    const int myIdx = gb >> 3;           // 0..255
    const int tc    = myIdx >> 6;        // t-chunk 0..3
    const int bbat  = myIdx & 63;        // batch
    const long bm = (long)bbat * TT + (long)tc * 128;
    const long bn = (long)nx * BN;

    const uint32_t aBase = (uint32_t)__cvta_generic_to_shared(As);
    const uint32_t bBase = (uint32_t)__cvta_generic_to_shared(Bs);

    const int cr = tid >> 2;
    const int cs = (tid & 3) * 8;

    auto issue = [&](int st, int k0) {
        cp_async16(aBase + (uint32_t)(st * BM * LDA + cr * LDA + cs) * 2,
                   A + (size_t)(bm + cr) * K + k0 + cs);
        cp_async16(bBase + (uint32_t)(st * BN * LDA + cr * LDA + cs) * 2,
                   Bw + (size_t)(bn + cr) * K + k0 + cs);
    };

    const int KT = K / BK;

    issue(0, 0);
    asm volatile("cp.async.commit_group;");
    issue(1, BK);
    asm volatile("cp.async.commit_group;");
    issue(2, 2 * BK);
    asm volatile("cp.async.commit_group;");

    float acc[2][4][4];
#pragma unroll
    for (int mf = 0; mf < 2; ++mf)
#pragma unroll
        for (int nt = 0; nt < 4; ++nt)
#pragma unroll
            for (int q = 0; q < 4; ++q) acc[mf][nt][q] = 0.0f;

    const int aRow  = wm * 32 + (lane & 15);
    const int aColH = (lane >> 4) << 3;
    const int bRow  = wn * 32 + (((lane >> 4) & 1) << 3) + (lane & 7);
    const int bColH = ((lane >> 3) & 1) << 3;

    for (int kt = 0; kt < KT; ++kt) {
        asm volatile("cp.async.wait_group 2;");
        __syncthreads();
        if (kt + 3 < KT) issue((kt + 3) & (ST - 1), (kt + 3) * BK);
        asm volatile("cp.async.commit_group;");

        const int st = kt & (ST - 1);
        const uint32_t aS = aBase + (uint32_t)(st * BM * LDA) * 2;
        const uint32_t bS = bBase + (uint32_t)(st * BN * LDA) * 2;

#pragma unroll
        for (int kf = 0; kf < 2; ++kf) {
            const int k0 = kf * 16;
            uint32_t afr[2][4];
#pragma unroll
            for (int mf = 0; mf < 2; ++mf)
                ldsm_x4(afr[mf], aS + (uint32_t)((aRow + mf * 16) * LDA + k0 + aColH) * 2);
            uint32_t bfr[2][4];
#pragma unroll
            for (int np = 0; np < 2; ++np)
                ldsm_x4(bfr[np], bS + (uint32_t)((bRow + np * 16) * LDA + k0 + bColH) * 2);
#pragma unroll
            for (int mf = 0; mf < 2; ++mf)
#pragma unroll
                for (int nt = 0; nt < 4; ++nt)
                    mma_bf16(acc[mf][nt], afr[mf], &bfr[nt >> 1][(nt & 1) * 2]);
        }
    }

#pragma unroll
    for (int mf = 0; mf < 2; ++mf) {
#pragma unroll
        for (int nt = 0; nt < 4; ++nt) {
            const long r0 = bm + wm * 32 + mf * 16 + (lane >> 2);
            const long c0 = bn + wn * 32 + nt * 8 + 2 * (lane & 3);
            const float bias0 = b1[c0] + b2[c0];
            const float bias1 = b1[c0 + 1] + b2[c0 + 1];
            C[r0 * N + c0]           = acc[mf][nt][0] + bias0;
            C[r0 * N + c0 + 1]       = acc[mf][nt][1] + bias1;
            C[(r0 + 8) * N + c0]     = acc[mf][nt][2] + bias0;
            C[(r0 + 8) * N + c0 + 1] = acc[mf][nt][3] + bias1;
        }
    }

    __syncthreads();
    if (tid == 0) {
        asm volatile("red.release.gpu.global.add.u32 [%0], 1;"
                     :: "l"(xgcnt + tc * 32) : "memory");
    }
}

// ---------------- fused 3-layer LSTM role, 32-batch group, warp dataflow sync --------
// MT=2 m-tiles (32 batches). 16 warps = 2(mi) x KSN(ks) x NTG(ntg).
template <int ROLE, int H, int KP, int HC, int FIRST, bool LAST_ONLY>
__device__ __forceinline__ void lstm_role(
    char* dyn,
    const float* __restrict__ xg,
    const float* __restrict__ Wih,
    const float* __restrict__ Whh,
    const float* __restrict__ bih,
    const float* __restrict__ bhh,
    const uint32_t* __restrict__ ringP, int strideP,
    uint32_t* __restrict__ ringR, int strideR,
    float* __restrict__ hlast,
    unsigned* __restrict__ flags,
    unsigned* __restrict__ xgcnt,
    int ctaLocal, int myflag, int bofs)
{
    constexpr int MB   = 32;                  // batches per group
    constexpr int MT   = 2;                   // m-tiles
    constexpr int COLS = 4 * HC;
    constexpr int GSW  = COLS + 2;
    constexpr int NT   = COLS / 8;
    constexpr int NTG  = NT / 4;              // L1:2 L2:1 L3:2
    constexpr int KSN  = 16 / (MT * NTG);     // L1:4 L2:8 L3:4
    constexpr int KB_P = (KP > 0) ? KP / 16 : 0;
    constexpr int KBT  = KB_P + H / 16;
    constexpr int KS   = KBT / KSN;           // L1:4 L2:3 L3:3
    constexpr int ELEMS = MB * HC;            // L1:512 L2:256 L3:512
    static_assert(KS * KSN == KBT, "k split");
    static_assert(NTG * 4 == NT, "n split");

    float* gS = (float*)dyn;                  // KSN slabs * MB * GSW

    const int tid  = threadIdx.x;
    const int lane = tid & 31;
    const int w    = tid >> 5;
    const int grp  = lane >> 2;
    const int th4  = lane & 3;
    const int h0   = ctaLocal * HC;

    const int mi    = w & 1;
    const int wr    = w >> 1;                 // 0..7
    const int ks    = wr & (KSN - 1);
    const int ntg_i = wr / KSN;

    // ---- per-lane wait assignment ----
    int fIdx = -1, fOff = 0;
    if (ROLE == 1) {
        if (lane < KS)       { fIdx = ks * KS + lane; fOff = 0; }        // L1 producers
        else if (lane < KS + 16) { fIdx = 16 + (lane - KS); fOff = -6; } // L2 backpressure
    } else if (ROLE == 2) {
        if (lane < 2 * KS) {                 // 6 lanes
            const int q = lane >> 1, r = lane & 1;
            const int kb = ks * KS + q;
            fIdx = (kb < 16) ? kb : (16 + 2 * (kb - 16) + r);
            fOff = 0;
        } else if (lane < 2 * KS + 4) { fIdx = 32 + (lane - 2 * KS); fOff = -6; }
    } else {
        if (lane < 2 * KS) {                 // 6 lanes
            const int q = lane >> 1, r = lane & 1;
            const int kb = ks * KS + q;
            fIdx = (kb < 8) ? (16 + 2 * kb + r) : (32 + (kb - 8));
            fOff = 0;
        }
    }
    unsigned* const fPtr = (fIdx >= 0) ? (flags + fIdx * 32) : flags;

    // ---- weight B fragments in registers ----
    uint32_t bw[KS][4][2];
    {
        const int colb = lane >> 2;
        const int kk0  = (lane & 3) * 2;
#pragma unroll
        for (int q = 0; q < KS; ++q) {
            const int kbg = ks * KS + q;
#pragma unroll
            for (int nip = 0; nip < 4; ++nip) {
                const int c = (ntg_i * 4 + nip) * 8 + colb;
                const int g = c / HC, u = c % HC;
                const int row = g * H + h0 + u;
#pragma unroll
                for (int j = 0; j < 2; ++j) {
                    const int k = kbg * 16 + kk0 + j * 8;
                    float w0, w1;
                    if (KP > 0 && k < KP) {
                        const float* p = Wih + (size_t)row * KP + k;
                        w0 = p[0]; w1 = p[1];
                    } else {
                        const float* p = Whh + (size_t)row * H + (k - KP);
                        w0 = p[0]; w1 = p[1];
                    }
                    bw[q][nip][j] = pack_h2(w0, w1);
                }
            }
        }
    }

    // ---- elementwise ownership: thread -> (batch b, unit jj), 1 element ----
    const bool ew = (ELEMS == 512) || (tid < ELEMS);
    const int b  = tid / HC;                  // 0..31
    const int jj = tid % HC;

    float cst = 0.0f;
    float xr[4];
    float bias[4];
    if (ew && KP > 0) {
        const int kme = h0 + jj;
#pragma unroll
        for (int g = 0; g < 4; ++g) {
            const int r = g * H + kme;
            bias[g] = bih[r] + bhh[r];
        }
    }

    // ROLE1: wait for xg t-chunk 0, then initial prefetch of xg[t=0]
    if (KP == 0) {
        if (tid == 0) {
            while (ld_acq(xgcnt) < 512u) { }
        }
        __syncthreads();
        if (ew) {
            const float* xp = xg + ((size_t)(bofs + b) * TT) * (4 * H) + h0 + jj;
#pragma unroll
            for (int g = 0; g < 4; ++g) xr[g] = xp[(size_t)g * H];
        }
    }

    // ---- output fragment half-index ----
    const int mib   = b >> 4;                 // 0..1
    const int r_    = b & 15;
    const int lanew = (r_ & 7) * 4 + ((jj & 7) >> 1);
    const int comp  = (HC == 16) ? (((jj >> 3) & 1) * 2 + (r_ >> 3))
                                 : ((ctaLocal & 1) * 2 + (r_ >> 3));
    const int kbOwn = (HC == 16) ? ctaLocal : (ctaLocal >> 1);
    const int out_u32 = kbOwn * 256 + (mib * 32 + lanew) * 4 + comp;

    __syncthreads();

    for (int s = 0; s < TOTS; ++s) {
        const int t = s - FIRST;
        const bool active = (t >= 0) && (t < TT);

        if (active) {
            // ---- warp-granular dataflow wait ----
            {
                const int thr = s + fOff;
                bool ok = (fIdx < 0) || (thr <= 0);
                const unsigned utg = (unsigned)thr;
                while (!__all_sync(0xffffffffu, ok)) {
                    if (!ok) ok = (ld_acq(fPtr) >= utg);
                }
            }

            // ROLE1: at t-chunk boundaries ensure NEXT xg chunk ready (prefetch reads t+1)
            if (KP == 0) {
                const int tn = t + 1;
                if (tn < TT && (tn & 127) == 0) {
                    if (tid == 0) {
                        unsigned* cp = xgcnt + (tn >> 7) * 32;
                        while (ld_acq(cp) < 512u) { }
                    }
                    __syncthreads();
                }
            }

            // ---- mma: A fragments direct from ring (L2) ----
            const uint32_t* srcP = (KP > 0) ? (ringP + (size_t)(t & (RING - 1)) * strideP)
                                            : (const uint32_t*)0;
            const uint32_t* srcR = ringR + (size_t)((t - 1) & (RING - 1)) * strideR;

            float4 avv[KS];
#pragma unroll
            for (int q = 0; q < KS; ++q) {
                const int kb = ks * KS + q;
                const uint32_t* p = (KP > 0 && kb < KB_P)
                                        ? (srcP + ((size_t)(kb * MT + mi) * 32 + lane) * 4)
                                        : (srcR + ((size_t)((kb - KB_P) * MT + mi) * 32 + lane) * 4);
                avv[q] = ldcg4(p);
            }

            float acc[4][4];
#pragma unroll
            for (int nip = 0; nip < 4; ++nip)
#pragma unroll
                for (int q = 0; q < 4; ++q) acc[nip][q] = 0.0f;

#pragma unroll
            for (int q = 0; q < KS; ++q) {
                const uint32_t* au = (const uint32_t*)&avv[q];
#pragma unroll
                for (int nip = 0; nip < 4; ++nip)
                    mma_f16(acc[nip], au, bw[q][nip]);
            }

            float* gr = gS + ks * (MB * GSW) + (mi * 16 + grp) * GSW + 2 * th4;
#pragma unroll
            for (int nip = 0; nip < 4; ++nip) {
                const int cc = (ntg_i * 4 + nip) * 8;
                gr[cc]               = acc[nip][0];
                gr[cc + 1]           = acc[nip][1];
                gr[8 * GSW + cc]     = acc[nip][2];
                gr[8 * GSW + cc + 1] = acc[nip][3];
            }
        }
        __syncthreads();

        // ---- activation + direct STG of h into ring ----
        if (active && ew) {
            uint32_t* dstR = ringR + (size_t)(t & (RING - 1)) * strideR;
            float pi, pf, pg, po;
            if (KP == 0) { pi = xr[0]; pf = xr[1]; pg = xr[2]; po = xr[3]; }
            else         { pi = bias[0]; pf = bias[1]; pg = bias[2]; po = bias[3]; }
#pragma unroll
            for (int sl = 0; sl < KSN; ++sl) {
                const float* row = gS + sl * (MB * GSW) + b * GSW;
                pi += row[jj];
                pf += row[HC + jj];
                pg += row[2 * HC + jj];
                po += row[3 * HC + jj];
            }
            const float iv = fast_sig(pi), fv = fast_sig(pf);
            const float gv = fast_tanh(pg), ov = fast_sig(po);
            cst = fv * cst + iv * gv;
            const float h = ov * fast_tanh(cst);

            ((__half*)dstR)[out_u32 * 2 + (jj & 1)] = __float2half(h);

            if (LAST_ONLY && t == TT - 1)
                hlast[(size_t)(bofs + b) * H + h0 + jj] = h;

            if (KP == 0 && t + 1 < TT) {
                const float* xp = xg + ((size_t)(bofs + b) * TT + (t + 1)) * (4 * H) + h0 + jj;
#pragma unroll
                for (int g = 0; g < 4; ++g) xr[g] = xp[(size_t)g * H];
            }
        }
        __syncthreads();   // order STGs before release

        if (tid == 0) {
            asm volatile("st.release.gpu.global.u32 [%0], %1;"
                         :: "l"(flags + myflag * 32), "r"((unsigned)(s + 1)) : "memory");
        }
    }
}

// ---------------- mega kernel: 72 lstm CTAs + 2048 gemm CTAs ----------------
__global__ __launch_bounds__(512, 1) void mega(
    const __nv_bfloat16* __restrict__ xbf, const __nv_bfloat16* __restrict__ W1bf,
    const float* __restrict__ bih1, const float* __restrict__ bhh1,
    float* __restrict__ xg1,
    const float* __restrict__ Whh1,
    const float* __restrict__ Wih2, const float* __restrict__ Whh2,
    const float* __restrict__ bih2, const float* __restrict__ bhh2,
    const float* __restrict__ Wih3, const float* __restrict__ Whh3,
    const float* __restrict__ bih3, const float* __restrict__ bhh3,
    float* __restrict__ h3out, unsigned* __restrict__ xgcnt)
{
    extern __shared__ char dynls[];
    const int cb = blockIdx.x;
    if (cb < NCTA_LSTM) {
        const int gidx = cb / 36;         // group 0/1
        const int lc   = cb % 36;
        unsigned* fl   = (unsigned*)g_flags + gidx * (36 * 32);
        const int bofs = gidx * 32;
        if (lc < 16) {
            lstm_role<1, H1, 0, 16, 0, false>(dynls, xg1, nullptr, Whh1, nullptr, nullptr,
                                              nullptr, 0, &g_b1[gidx][0][0], 4096, nullptr,
                                              fl, xgcnt, lc, lc, bofs);
        } else if (lc < 32) {
            lstm_role<2, H2, H1, 8, 1, false>(dynls, nullptr, Wih2, Whh2, bih2, bhh2,
                                              &g_b1[gidx][0][0], 4096, &g_b2[gidx][0][0], 2048,
                                              nullptr, fl, xgcnt, lc - 16, lc, bofs);
        } else {
            lstm_role<3, H3, H2, 16, 2, true>(dynls, nullptr, Wih3, Whh3, bih3, bhh3,
                                              &g_b2[gidx][0][0], 2048, &g_b3[gidx][0][0], 1024,
                                              h3out, fl, xgcnt, lc - 32, lc, bofs);
        }
    } else {
        gemm_body(dynls, cb - NCTA_LSTM, xbf, W1bf, bih1, bhh1, xg1, xgcnt);
    }
}

// ---------------- head: deep/wide/concat/output (256 threads) ----------------
__global__ __launch_bounds__(256) void head_kernel(
    const float* __restrict__ x,
    const float* __restrict__ h3last,
    const float* __restrict__ Wd, const float* __restrict__ bd,
    const float* __restrict__ Ww, const float* __restrict__ bw,
    const float* __restrict__ Wo, const float* __restrict__ bo,
    float* __restrict__ out)
{
    const int bidx = blockIdx.x;
    const int j = threadIdx.x & 31;
    const int s = threadIdx.x >> 5;
    __shared__ float red[8][33];

    const float* xrow = x + ((size_t)bidx * TT + (TT - 1)) * DD;
    const float* wwr = Ww + (size_t)j * DD;
    float acc = 0.0f;
    const int k0 = s * (DD / 8);
#pragma unroll 4
    for (int k = k0; k < k0 + DD / 8; k += 4) {
        const float4 xv = *(const float4*)&xrow[k];
        const float4 wv = *(const float4*)&wwr[k];
        acc = fmaf(xv.x, wv.x, acc);
        acc = fmaf(xv.y, wv.y, acc);
        acc = fmaf(xv.z, wv.z, acc);
        acc = fmaf(xv.w, wv.w, acc);
    }
    red[s][j] = acc;
    __syncthreads();

    if (s == 0) {
        float wide = bw[j];
#pragma unroll
        for (int q = 0; q < 8; ++q) wide += red[q][j];
        wide = fmaxf(wide, 0.0f);

        const float* hrow = h3last + (size_t)bidx * H3;
        const float* wdr = Wd + (size_t)j * H3;
        float deep = bd[j];
#pragma unroll
        for (int k = 0; k < H3; ++k) deep = fmaf(hrow[k], wdr[k], deep);
        deep = fmaxf(deep, 0.0f);

        float v = deep * Wo[j] + wide * Wo[32 + j];
#pragma unroll
        for (int off = 16; off > 0; off >>= 1)
            v += __shfl_xor_sync(0xffffffffu, v, off);
        if (j == 0) out[bidx] = v + bo[0];
    }
}

// ---------------- launch ----------------
extern "C" void kernel_launch(void* const* d_in, const int* in_sizes, int n_in,
                              void* d_out, int out_size) {
    const float* x    = (const float*)d_in[0];
    const float* Wih1 = (const float*)d_in[1];
    const float* Whh1 = (const float*)d_in[2];
    const float* bih1 = (const float*)d_in[3];
    const float* bhh1 = (const float*)d_in[4];
    const float* Wih2 = (const float*)d_in[5];
    const float* Whh2 = (const float*)d_in[6];
    const float* bih2 = (const float*)d_in[7];
    const float* bhh2 = (const float*)d_in[8];
    const float* Wih3 = (const float*)d_in[9];
    const float* Whh3 = (const float*)d_in[10];
    const float* bih3 = (const float*)d_in[11];
    const float* bhh3 = (const float*)d_in[12];
    const float* Wd   = (const float*)d_in[13];
    const float* bd   = (const float*)d_in[14];
    const float* Ww   = (const float*)d_in[15];
    const float* bw   = (const float*)d_in[16];
    const float* Wo   = (const float*)d_in[17];
    const float* bo   = (const float*)d_in[18];
    float* out = (float*)d_out;

    float *xg1, *h3;
    __nv_bfloat16 *xbf, *W1bf;
    unsigned* xgcnt;
    cudaGetSymbolAddress((void**)&xg1,   g_xg1);
    cudaGetSymbolAddress((void**)&h3,    g_h3);
    cudaGetSymbolAddress((void**)&xbf,   g_xbf);
    cudaGetSymbolAddress((void**)&W1bf,  g_W1bf);
    cudaGetSymbolAddress((void**)&xgcnt, g_xgcnt);

    prep_zero<<<120, 512>>>();

    // convert x and Wih1 to bf16 for the big GEMM
    f2bf_kernel<<<4096, 256>>>(x,    xbf,  (BB * TT * DD) / 4);
    f2bf_kernel<<<512,  256>>>(Wih1, W1bf, (4 * H1 * DD) / 4);

    // mega kernel: gemm (producer, t-chunk-ordered) + 2 batch-group recurrences
    {
        const int dynBytes = 4 * (128 + 128) * 40 * 2;   // 81920 (gemm; lstm max ~34.8KB)
        cudaFuncSetAttribute(mega, cudaFuncAttributeMaxDynamicSharedMemorySize, dynBytes);
        mega<<<NCTA_LSTM + NCTA_GEMM, 512, dynBytes>>>(
            xbf, W1bf, bih1, bhh1, xg1,
            Whh1, Wih2, Whh2, bih2, bhh2,
            Wih3, Whh3, bih3, bhh3,
            h3, xgcnt);
    }

    // head
    head_kernel<<<BB, 256>>>(x, h3, Wd, bd, Ww, bw, Wo, bo, out);

    (void)in_sizes; (void)n_in; (void)out_size;
}